// round 1
// baseline (speedup 1.0000x reference)
#include <cuda_runtime.h>

// Problem constants
#define Bc  64
#define Mc  512
#define Hc  1024
#define NHc 8
#define HDc 128
#define EPSc 1e-5f

// ---------------------------------------------------------------------------
// Scratch (static device globals — allocation-free)
// ---------------------------------------------------------------------------
__device__ float g_mw, g_mb;
__device__ float g_xa  [(size_t)Bc*Mc*Mc];       // affine(x)            64 MB
__device__ float g_h1  [(size_t)Bc*Mc*Hc];       // relu(x@w1+b1)       128 MB
__device__ float g_xreg[(size_t)Bc*Mc*Hc];       // x_reg               128 MB
__device__ float g_xn  [(size_t)Bc*Mc*Hc];       // layernorm           128 MB
__device__ float g_q   [(size_t)Bc*Mc*Hc];
__device__ float g_k   [(size_t)Bc*Mc*Hc];
__device__ float g_v   [(size_t)Bc*Mc*Hc];
__device__ float g_s   [(size_t)Bc*NHc*Mc*Mc];   // scores/attn         512 MB
__device__ float g_ctx [(size_t)Bc*Mc*Hc];
__device__ float g_t1  [(size_t)Bc*Mc*Hc];

// ---------------------------------------------------------------------------
// conv_w/conv_b means (H=1024, one block of 1024 threads)
// ---------------------------------------------------------------------------
__global__ void means_k(const float* __restrict__ w, const float* __restrict__ b) {
    __shared__ float sw[32], sb[32];
    int t = threadIdx.x;
    float vw = w[t], vb = b[t];
    #pragma unroll
    for (int o = 16; o > 0; o >>= 1) {
        vw += __shfl_down_sync(0xffffffffu, vw, o);
        vb += __shfl_down_sync(0xffffffffu, vb, o);
    }
    if ((t & 31) == 0) { sw[t >> 5] = vw; sb[t >> 5] = vb; }
    __syncthreads();
    if (t < 32) {
        vw = sw[t]; vb = sb[t];
        #pragma unroll
        for (int o = 16; o > 0; o >>= 1) {
            vw += __shfl_down_sync(0xffffffffu, vw, o);
            vb += __shfl_down_sync(0xffffffffu, vb, o);
        }
        if (t == 0) { g_mw = vw / (float)Hc; g_mb = vb / (float)Hc; }
    }
}

// ---------------------------------------------------------------------------
// y = x*(1+mean_w) + mean_b   (vectorized float4)
// ---------------------------------------------------------------------------
__global__ void affine_k(const float4* __restrict__ x, float4* __restrict__ y) {
    long i = (long)blockIdx.x * blockDim.x + threadIdx.x;
    float a = 1.0f + g_mw, c = g_mb;
    float4 v = x[i];
    v.x = v.x * a + c; v.y = v.y * a + c; v.z = v.z * a + c; v.w = v.w * a + c;
    y[i] = v;
}

// ---------------------------------------------------------------------------
// Generic tiled SGEMM: C = alpha*(A@B) [+bias] [relu] [+res]
// A: [M,K] row-major (lda). B: NN -> [K,N] row-major (ldb); NT -> [N,K] (ldb).
// Batched via blockIdx.z with 2-level strides: off = (z/nh)*s0 + (z%nh)*s1.
// BM=BN=128, BK=8, 256 threads, 8x8 per thread.
// ---------------------------------------------------------------------------
#define BM 128
#define BN 128
#define BK 8

template<bool NT, bool RELU, bool RES>
__global__ void __launch_bounds__(256)
sgemm(const float* __restrict__ Ab, const float* __restrict__ Bb,
      const float* __restrict__ bias, const float* __restrict__ Rb,
      float* __restrict__ Cb,
      int Kdim, int lda, int ldb, int ldc,
      int nh, long sA0, long sA1, long sB0, long sB1, long sC0, long sC1,
      float alpha)
{
    int z = blockIdx.z;
    long zb = z / nh, zh = z % nh;
    const float* A = Ab + zb * sA0 + zh * sA1;
    const float* Bp = Bb + zb * sB0 + zh * sB1;
    float*       C = Cb + zb * sC0 + zh * sC1;
    const float* R = RES ? (Rb + zb * sC0 + zh * sC1) : nullptr;

    __shared__ float As[BK][BM];
    __shared__ float Bs[BK][BN];

    int tid = threadIdx.x;
    int tx = tid & 15, ty = tid >> 4;
    int row0 = blockIdx.y * BM;
    int col0 = blockIdx.x * BN;

    float acc[8][8];
    #pragma unroll
    for (int i = 0; i < 8; i++)
        #pragma unroll
        for (int j = 0; j < 8; j++) acc[i][j] = 0.0f;

    int arow = tid >> 1;            // 0..127
    int acol = (tid & 1) * 4;       // 0 / 4
    int brow = tid >> 5;            // 0..7  (NN)
    int bcol = (tid & 31) * 4;      // 0..124
    int ntn  = tid >> 1;            // 0..127 (NT)
    int ntk  = (tid & 1) * 4;

    for (int k0 = 0; k0 < Kdim; k0 += BK) {
        float4 av = *(const float4*)(A + (long)(row0 + arow) * lda + k0 + acol);
        As[acol + 0][arow] = av.x;
        As[acol + 1][arow] = av.y;
        As[acol + 2][arow] = av.z;
        As[acol + 3][arow] = av.w;
        if (NT) {
            float4 bv = *(const float4*)(Bp + (long)(col0 + ntn) * ldb + k0 + ntk);
            Bs[ntk + 0][ntn] = bv.x;
            Bs[ntk + 1][ntn] = bv.y;
            Bs[ntk + 2][ntn] = bv.z;
            Bs[ntk + 3][ntn] = bv.w;
        } else {
            float4 bv = *(const float4*)(Bp + (long)(k0 + brow) * ldb + col0 + bcol);
            *(float4*)&Bs[brow][bcol] = bv;
        }
        __syncthreads();

        #pragma unroll
        for (int k = 0; k < BK; k++) {
            float ra[8], rb[8];
            #pragma unroll
            for (int i = 0; i < 8; i++) ra[i] = As[k][ty * 8 + i];
            #pragma unroll
            for (int j = 0; j < 8; j++) rb[j] = Bs[k][tx * 8 + j];
            #pragma unroll
            for (int i = 0; i < 8; i++)
                #pragma unroll
                for (int j = 0; j < 8; j++) acc[i][j] += ra[i] * rb[j];
        }
        __syncthreads();
    }

    #pragma unroll
    for (int i = 0; i < 8; i++) {
        long r = row0 + ty * 8 + i;
        #pragma unroll
        for (int j = 0; j < 8; j += 4) {
            long c = col0 + tx * 8 + j;
            float4 v;
            v.x = acc[i][j + 0] * alpha;
            v.y = acc[i][j + 1] * alpha;
            v.z = acc[i][j + 2] * alpha;
            v.w = acc[i][j + 3] * alpha;
            if (bias) {
                v.x += bias[c + 0]; v.y += bias[c + 1];
                v.z += bias[c + 2]; v.w += bias[c + 3];
            }
            if (RELU) {
                v.x = fmaxf(v.x, 0.0f); v.y = fmaxf(v.y, 0.0f);
                v.z = fmaxf(v.z, 0.0f); v.w = fmaxf(v.w, 0.0f);
            }
            if (RES) {
                const float4 rv = *(const float4*)(R + r * ldc + c);
                v.x += rv.x; v.y += rv.y; v.z += rv.z; v.w += rv.w;
            }
            *(float4*)(C + r * ldc + c) = v;
        }
    }
}

// ---------------------------------------------------------------------------
// LayerNorm over H=1024, one block (256 thr) per row
// ---------------------------------------------------------------------------
__global__ void ln_k(const float* __restrict__ in, const float* __restrict__ g,
                     const float* __restrict__ be, float* __restrict__ out)
{
    long row = blockIdx.x;
    const float4* p = (const float4*)(in + row * Hc);
    float4*       o = (float4*)(out + row * Hc);
    int t = threadIdx.x;
    float4 v = p[t];
    float s  = v.x + v.y + v.z + v.w;
    float s2 = v.x * v.x + v.y * v.y + v.z * v.z + v.w * v.w;
    __shared__ float ss[8], ss2[8];
    #pragma unroll
    for (int of = 16; of > 0; of >>= 1) {
        s  += __shfl_down_sync(0xffffffffu, s, of);
        s2 += __shfl_down_sync(0xffffffffu, s2, of);
    }
    if ((t & 31) == 0) { ss[t >> 5] = s; ss2[t >> 5] = s2; }
    __syncthreads();
    __shared__ float mu_s, ri_s;
    if (t == 0) {
        float a = 0.f, b2 = 0.f;
        #pragma unroll
        for (int i = 0; i < 8; i++) { a += ss[i]; b2 += ss2[i]; }
        float mu = a / (float)Hc;
        float var = b2 / (float)Hc - mu * mu;
        mu_s = mu;
        ri_s = rsqrtf(var + EPSc);
    }
    __syncthreads();
    float mu = mu_s, ri = ri_s;
    float4 gv = ((const float4*)g)[t];
    float4 bv = ((const float4*)be)[t];
    float4 r;
    r.x = (v.x - mu) * ri * gv.x + bv.x;
    r.y = (v.y - mu) * ri * gv.y + bv.y;
    r.z = (v.z - mu) * ri * gv.z + bv.z;
    r.w = (v.w - mu) * ri * gv.w + bv.w;
    o[t] = r;
}

// ---------------------------------------------------------------------------
// Softmax over M=512 with diagonal score zeroed BEFORE softmax (mask * score,
// not -inf!). One block (128 thr, float4 each) per row. Row = bh*512 + q.
// ---------------------------------------------------------------------------
__global__ void softmax_k(float* __restrict__ s)
{
    long row = blockIdx.x;
    int  qi  = (int)(row & (Mc - 1));
    float4* p = (float4*)(s + row * Mc);
    int t = threadIdx.x;
    float4 v = p[t];
    int c0 = t * 4;
    if (qi >= c0 && qi < c0 + 4) ((float*)&v)[qi - c0] = 0.0f;  // zero diag score

    float m = fmaxf(fmaxf(v.x, v.y), fmaxf(v.z, v.w));
    __shared__ float sm[4];
    #pragma unroll
    for (int of = 16; of > 0; of >>= 1) m = fmaxf(m, __shfl_xor_sync(0xffffffffu, m, of));
    if ((t & 31) == 0) sm[t >> 5] = m;
    __syncthreads();
    m = fmaxf(fmaxf(sm[0], sm[1]), fmaxf(sm[2], sm[3]));

    v.x = expf(v.x - m); v.y = expf(v.y - m);
    v.z = expf(v.z - m); v.w = expf(v.w - m);
    float su = v.x + v.y + v.z + v.w;
    __shared__ float ssum[4];
    #pragma unroll
    for (int of = 16; of > 0; of >>= 1) su += __shfl_xor_sync(0xffffffffu, su, of);
    if ((t & 31) == 0) ssum[t >> 5] = su;
    __syncthreads();
    su = ssum[0] + ssum[1] + ssum[2] + ssum[3];
    float r = 1.0f / su;
    v.x *= r; v.y *= r; v.z *= r; v.w *= r;
    p[t] = v;
}

// ---------------------------------------------------------------------------
// Launch
// ---------------------------------------------------------------------------
extern "C" void kernel_launch(void* const* d_in, const int* in_sizes, int n_in,
                              void* d_out, int out_size)
{
    const float* x      = (const float*)d_in[0];
    const float* conv_w = (const float*)d_in[1];
    const float* conv_b = (const float*)d_in[2];
    const float* w1 = (const float*)d_in[3];
    const float* b1 = (const float*)d_in[4];
    const float* w2 = (const float*)d_in[5];
    const float* b2 = (const float*)d_in[6];
    const float* ln_g = (const float*)d_in[7];
    const float* ln_b = (const float*)d_in[8];
    const float* wq = (const float*)d_in[9];
    const float* bq = (const float*)d_in[10];
    const float* wk = (const float*)d_in[11];
    const float* bk = (const float*)d_in[12];
    const float* wv = (const float*)d_in[13];
    const float* bv = (const float*)d_in[14];
    const float* wo = (const float*)d_in[15];
    const float* bo = (const float*)d_in[16];
    const float* wp = (const float*)d_in[17];
    const float* bp = (const float*)d_in[18];
    float* out = (float*)d_out;

    float *xa, *h1, *xreg, *xn, *q, *k, *v, *s, *ctx, *t1;
    cudaGetSymbolAddress((void**)&xa,   g_xa);
    cudaGetSymbolAddress((void**)&h1,   g_h1);
    cudaGetSymbolAddress((void**)&xreg, g_xreg);
    cudaGetSymbolAddress((void**)&xn,   g_xn);
    cudaGetSymbolAddress((void**)&q,    g_q);
    cudaGetSymbolAddress((void**)&k,    g_k);
    cudaGetSymbolAddress((void**)&v,    g_v);
    cudaGetSymbolAddress((void**)&s,    g_s);
    cudaGetSymbolAddress((void**)&ctx,  g_ctx);
    cudaGetSymbolAddress((void**)&t1,   g_t1);

    const int BMrows = Bc * Mc;               // 32768
    const long MH = (long)Mc * Hc;            // per-batch stride of [M,H]
    const long MM = (long)Mc * Mc;            // per-head score tile

    // 1. means of conv_w / conv_b
    means_k<<<1, 1024>>>(conv_w, conv_b);

    // 2. affine: xa = x*(1+mw)+mb
    {
        long n4 = (long)Bc * Mc * Mc / 4;     // 4,194,304
        affine_k<<<(unsigned)(n4 / 256), 256>>>((const float4*)x, (float4*)xa);
    }

    // 3. h1 = relu(xa @ w1 + b1)     [32768,512]x[512,1024]
    sgemm<false, true, false><<<dim3(Hc / BN, BMrows / BM, 1), 256>>>(
        xa, w1, b1, nullptr, h1, Mc, Mc, Hc, Hc,
        1, 0, 0, 0, 0, 0, 0, 1.0f);

    // 4. xreg = h1 @ w2 + b2         [32768,1024]x[1024,1024]
    sgemm<false, false, false><<<dim3(Hc / BN, BMrows / BM, 1), 256>>>(
        h1, w2, b2, nullptr, xreg, Hc, Hc, Hc, Hc,
        1, 0, 0, 0, 0, 0, 0, 1.0f);

    // 5. layernorm
    ln_k<<<BMrows, 256>>>(xreg, ln_g, ln_b, xn);

    // 6. q/k/v projections
    sgemm<false, false, false><<<dim3(Hc / BN, BMrows / BM, 1), 256>>>(
        xn, wq, bq, nullptr, q, Hc, Hc, Hc, Hc, 1, 0, 0, 0, 0, 0, 0, 1.0f);
    sgemm<false, false, false><<<dim3(Hc / BN, BMrows / BM, 1), 256>>>(
        xn, wk, bk, nullptr, k, Hc, Hc, Hc, Hc, 1, 0, 0, 0, 0, 0, 0, 1.0f);
    sgemm<false, false, false><<<dim3(Hc / BN, BMrows / BM, 1), 256>>>(
        xn, wv, bv, nullptr, v, Hc, Hc, Hc, Hc, 1, 0, 0, 0, 0, 0, 0, 1.0f);

    // 7. scores = (Q @ K^T) / sqrt(HD), batched over b*h = 512
    //    A = q + b*M*H + h*HD (lda=H), B = k likewise (NT), C = s + z*M*M
    const float alpha = 0.08838834764831845f;  // 1/sqrt(128)
    sgemm<true, false, false><<<dim3(Mc / BN, Mc / BM, Bc * NHc), 256>>>(
        q, k, nullptr, nullptr, s, HDc, Hc, Hc, Mc,
        NHc, MH, HDc, MH, HDc, (long)NHc * MM, MM, alpha);

    // 8. zero-diag + softmax (fused), one block per score row
    softmax_k<<<Bc * NHc * Mc, 128>>>(s);

    // 9. ctx = attn @ V, batched: [512,512]x[512,128] per head
    sgemm<false, false, false><<<dim3(HDc / BN, Mc / BM, Bc * NHc), 256>>>(
        s, v, nullptr, nullptr, ctx, Mc, Mc, Hc, Hc,
        NHc, (long)NHc * MM, MM, MH, HDc, MH, HDc, 1.0f);

    // 10. t1 = ctx @ wo + bo
    sgemm<false, false, false><<<dim3(Hc / BN, BMrows / BM, 1), 256>>>(
        ctx, wo, bo, nullptr, t1, Hc, Hc, Hc, Hc, 1, 0, 0, 0, 0, 0, 0, 1.0f);

    // 11. out = t1 @ wp + bp + xreg
    sgemm<false, false, true><<<dim3(Hc / BN, BMrows / BM, 1), 256>>>(
        t1, wp, bp, xreg, out, Hc, Hc, Hc, Hc, 1, 0, 0, 0, 0, 0, 0, 1.0f);
}

// round 3
// speedup vs baseline: 2.9287x; 2.9287x over previous
#include <cuda_runtime.h>
#include <cuda_bf16.h>
#include <cstdint>

#define Bc  64
#define Mc  512
#define Hc  1024
#define NHc 8
#define HDc 128
#define EPSc 1e-5f

typedef __nv_bfloat16 bf16;

#define BMH ((size_t)Bc*Mc*Hc)
#define BMM ((size_t)Bc*Mc*Mc)
#define SMM ((size_t)Bc*NHc*Mc*Mc)

// ---------------------------------------------------------------------------
// Scratch (static device globals — allocation-free)
// ---------------------------------------------------------------------------
__device__ float g_mw, g_mb;
__device__ bf16 g_xah[BMM], g_xal[BMM];
__device__ bf16 g_h1h[BMH], g_h1l[BMH];
__device__ float g_xreg[BMH];
__device__ bf16 g_xnh[BMH], g_xnl[BMH];
__device__ bf16 g_qh[BMH], g_ql[BMH], g_kh[BMH], g_kl[BMH];
__device__ float g_v[BMH];
__device__ bf16 g_vth[BMH], g_vtl[BMH];           // [B*NH, 128, 512]
__device__ float g_s[SMM];
__device__ bf16 g_sh[SMM], g_sl[SMM];
__device__ bf16 g_ch[BMH], g_cl[BMH];
__device__ bf16 g_t1h[BMH], g_t1l[BMH];
// transposed + split weights  [N, K]
__device__ bf16 g_w1h[(size_t)Hc*Mc],  g_w1l[(size_t)Hc*Mc];
__device__ bf16 g_w2h[(size_t)Hc*Hc],  g_w2l[(size_t)Hc*Hc];
__device__ bf16 g_wqh[(size_t)Hc*Hc],  g_wql[(size_t)Hc*Hc];
__device__ bf16 g_wkh[(size_t)Hc*Hc],  g_wkl[(size_t)Hc*Hc];
__device__ bf16 g_wvh[(size_t)Hc*Hc],  g_wvl[(size_t)Hc*Hc];
__device__ bf16 g_woh[(size_t)Hc*Hc],  g_wol[(size_t)Hc*Hc];
__device__ bf16 g_wph[(size_t)Hc*Hc],  g_wpl[(size_t)Hc*Hc];

// ---------------------------------------------------------------------------
// PTX helpers (baseline PTX only — no tcgen05 on compute_103)
// ---------------------------------------------------------------------------
__device__ __forceinline__ uint32_t smem_u32(const void* p) {
    uint32_t a;
    asm("{ .reg .u64 t; cvta.to.shared.u64 t, %1; cvt.u32.u64 %0, t; }"
        : "=r"(a) : "l"(p));
    return a;
}

__device__ __forceinline__ void cp_async16(uint32_t saddr, const void* gaddr) {
    asm volatile("cp.async.cg.shared.global [%0], [%1], 16;\n"
                 :: "r"(saddr), "l"(gaddr));
}
__device__ __forceinline__ void cp_commit() {
    asm volatile("cp.async.commit_group;\n" ::: "memory");
}
template<int N>
__device__ __forceinline__ void cp_wait() {
    asm volatile("cp.async.wait_group %0;\n" :: "n"(N) : "memory");
}

__device__ __forceinline__ void ldsm4(uint32_t& r0, uint32_t& r1, uint32_t& r2, uint32_t& r3,
                                      uint32_t addr) {
    asm volatile("ldmatrix.sync.aligned.m8n8.x4.shared.b16 {%0,%1,%2,%3}, [%4];"
                 : "=r"(r0), "=r"(r1), "=r"(r2), "=r"(r3) : "r"(addr));
}

__device__ __forceinline__ void mma16816(float* c, const uint32_t* a, uint32_t b0, uint32_t b1) {
    asm volatile("mma.sync.aligned.m16n8k16.row.col.f32.bf16.bf16.f32 "
                 "{%0,%1,%2,%3}, {%4,%5,%6,%7}, {%8,%9}, {%0,%1,%2,%3};"
                 : "+f"(c[0]), "+f"(c[1]), "+f"(c[2]), "+f"(c[3])
                 : "r"(a[0]), "r"(a[1]), "r"(a[2]), "r"(a[3]), "r"(b0), "r"(b1));
}

// ---------------------------------------------------------------------------
// small kernels
// ---------------------------------------------------------------------------
__global__ void means_k(const float* __restrict__ w, const float* __restrict__ b) {
    __shared__ float sw[32], sb[32];
    int t = threadIdx.x;
    float vw = w[t], vb = b[t];
    #pragma unroll
    for (int o = 16; o > 0; o >>= 1) {
        vw += __shfl_down_sync(0xffffffffu, vw, o);
        vb += __shfl_down_sync(0xffffffffu, vb, o);
    }
    if ((t & 31) == 0) { sw[t >> 5] = vw; sb[t >> 5] = vb; }
    __syncthreads();
    if (t < 32) {
        vw = sw[t]; vb = sb[t];
        #pragma unroll
        for (int o = 16; o > 0; o >>= 1) {
            vw += __shfl_down_sync(0xffffffffu, vw, o);
            vb += __shfl_down_sync(0xffffffffu, vb, o);
        }
        if (t == 0) { g_mw = vw / (float)Hc; g_mb = vb / (float)Hc; }
    }
}

__device__ __forceinline__ void split_store4(bf16* __restrict__ ph, bf16* __restrict__ pl,
                                             float v0, float v1, float v2, float v3) {
    bf16 h0 = __float2bfloat16(v0), h1 = __float2bfloat16(v1);
    bf16 h2 = __float2bfloat16(v2), h3 = __float2bfloat16(v3);
    ((__nv_bfloat162*)ph)[0] = __halves2bfloat162(h0, h1);
    ((__nv_bfloat162*)ph)[1] = __halves2bfloat162(h2, h3);
    ((__nv_bfloat162*)pl)[0] = __halves2bfloat162(
        __float2bfloat16(v0 - __bfloat162float(h0)), __float2bfloat16(v1 - __bfloat162float(h1)));
    ((__nv_bfloat162*)pl)[1] = __halves2bfloat162(
        __float2bfloat16(v2 - __bfloat162float(h2)), __float2bfloat16(v3 - __bfloat162float(h3)));
}

__global__ void affine_k(const float4* __restrict__ x, bf16* __restrict__ xh, bf16* __restrict__ xl) {
    long i = (long)blockIdx.x * blockDim.x + threadIdx.x;
    float a = 1.0f + g_mw, c = g_mb;
    float4 v = x[i];
    split_store4(xh + i * 4, xl + i * 4, v.x * a + c, v.y * a + c, v.z * a + c, v.w * a + c);
}

// W [K,N] fp32 -> WT_hi/lo [N,K] bf16
__global__ void wsplitT(const float* __restrict__ W, bf16* __restrict__ th, bf16* __restrict__ tl,
                        int K, int N) {
    __shared__ float t[32][33];
    int k0 = blockIdx.x * 32, n0 = blockIdx.y * 32;
    int tx = threadIdx.x, ty = threadIdx.y;
    #pragma unroll
    for (int i = ty; i < 32; i += 8)
        t[i][tx] = W[(long)(k0 + i) * N + n0 + tx];
    __syncthreads();
    #pragma unroll
    for (int i = ty; i < 32; i += 8) {
        float v = t[tx][i];                 // = W[k0+tx][n0+i]
        bf16 h = __float2bfloat16(v);
        long o = (long)(n0 + i) * K + k0 + tx;
        th[o] = h;
        tl[o] = __float2bfloat16(v - __bfloat162float(h));
    }
}

// v fp32 [B*M, H] -> vT_hi/lo [(B*NH), HD, M]
__global__ void vsplitT(const float* __restrict__ v, bf16* __restrict__ th, bf16* __restrict__ tl) {
    __shared__ float t[32][33];
    int z = blockIdx.z, zb = z >> 3, zh = z & 7;
    int m0 = blockIdx.x * 32, d0 = blockIdx.y * 32;
    int tx = threadIdx.x, ty = threadIdx.y;
    #pragma unroll
    for (int i = ty; i < 32; i += 8)
        t[i][tx] = v[((long)zb * Mc + m0 + i) * Hc + zh * HDc + d0 + tx];
    __syncthreads();
    #pragma unroll
    for (int i = ty; i < 32; i += 8) {
        float val = t[tx][i];               // v[token m0+tx][hd d0+i]
        bf16 h = __float2bfloat16(val);
        long o = ((long)z * HDc + d0 + i) * Mc + m0 + tx;
        th[o] = h;
        tl[o] = __float2bfloat16(val - __bfloat162float(h));
    }
}

__global__ void ln_k(const float* __restrict__ in, const float* __restrict__ g,
                     const float* __restrict__ be, bf16* __restrict__ oh, bf16* __restrict__ ol) {
    long row = blockIdx.x;
    const float4* p = (const float4*)(in + row * Hc);
    int t = threadIdx.x;
    float4 v = p[t];
    float s  = v.x + v.y + v.z + v.w;
    float s2 = v.x * v.x + v.y * v.y + v.z * v.z + v.w * v.w;
    __shared__ float ss[8], ss2[8];
    #pragma unroll
    for (int of = 16; of > 0; of >>= 1) {
        s  += __shfl_down_sync(0xffffffffu, s, of);
        s2 += __shfl_down_sync(0xffffffffu, s2, of);
    }
    if ((t & 31) == 0) { ss[t >> 5] = s; ss2[t >> 5] = s2; }
    __syncthreads();
    __shared__ float mu_s, ri_s;
    if (t == 0) {
        float a = 0.f, b2 = 0.f;
        #pragma unroll
        for (int i = 0; i < 8; i++) { a += ss[i]; b2 += ss2[i]; }
        float mu = a / (float)Hc;
        mu_s = mu;
        ri_s = rsqrtf(b2 / (float)Hc - mu * mu + EPSc);
    }
    __syncthreads();
    float mu = mu_s, ri = ri_s;
    float4 gv = ((const float4*)g)[t];
    float4 bv = ((const float4*)be)[t];
    long o = row * Hc + t * 4;
    split_store4(oh + o, ol + o,
                 (v.x - mu) * ri * gv.x + bv.x, (v.y - mu) * ri * gv.y + bv.y,
                 (v.z - mu) * ri * gv.z + bv.z, (v.w - mu) * ri * gv.w + bv.w);
}

__global__ void softmax_k(const float* __restrict__ s, bf16* __restrict__ sh, bf16* __restrict__ sl) {
    long row = blockIdx.x;
    int  qi  = (int)(row & (Mc - 1));
    const float4* p = (const float4*)(s + row * Mc);
    int t = threadIdx.x;
    float4 v = p[t];
    int c0 = t * 4;
    if (qi >= c0 && qi < c0 + 4) ((float*)&v)[qi - c0] = 0.0f;

    float m = fmaxf(fmaxf(v.x, v.y), fmaxf(v.z, v.w));
    __shared__ float sm[4];
    #pragma unroll
    for (int of = 16; of > 0; of >>= 1) m = fmaxf(m, __shfl_xor_sync(0xffffffffu, m, of));
    if ((t & 31) == 0) sm[t >> 5] = m;
    __syncthreads();
    m = fmaxf(fmaxf(sm[0], sm[1]), fmaxf(sm[2], sm[3]));

    v.x = expf(v.x - m); v.y = expf(v.y - m);
    v.z = expf(v.z - m); v.w = expf(v.w - m);
    float su = v.x + v.y + v.z + v.w;
    __shared__ float ssum[4];
    #pragma unroll
    for (int of = 16; of > 0; of >>= 1) su += __shfl_xor_sync(0xffffffffu, su, of);
    if ((t & 31) == 0) ssum[t >> 5] = su;
    __syncthreads();
    su = ssum[0] + ssum[1] + ssum[2] + ssum[3];
    float r = 1.0f / su;
    long o = row * Mc + t * 4;
    split_store4(sh + o, sl + o, v.x * r, v.y * r, v.z * r, v.w * r);
}

// ---------------------------------------------------------------------------
// mma.sync split-bf16 GEMM: C[M,N] = alpha * (A @ B^T) (+bias)(relu)(+res)
//   A rows [*, lda] bf16 hi/lo; B rows [N, ldb] bf16 hi/lo (K-major, NT).
//   BM=128, BN=128, BK=64, 256 thr = 8 warps (2x4), warp tile 64x32.
//   3-stage cp.async pipeline; XOR-swizzled smem; ldmatrix fragments.
// EPI bits: 1=bias, 2=relu, 4=residual, 8=split-bf16 output (else fp32)
// ---------------------------------------------------------------------------
#define NST 3
#define TILEB 16384                 // one 128x64 bf16 tile
#define STAGEB (4 * TILEB)          // Ah, Al, Bh, Bl

// issue cp.async for one 128x64 bf16 tile
__device__ __forceinline__ void tile_cp(uint32_t sm, const bf16* __restrict__ g, long ld, int tid) {
    int r = tid >> 3;              // 0..31
    int c16 = tid & 7;             // 16B column unit
    const char* gp = (const char*)(g + c16 * 8);
    #pragma unroll
    for (int i = 0; i < 4; i++) {
        int row = r + i * 32;
        uint32_t so = sm + row * 128 + ((c16 ^ (row & 7)) << 4);
        cp_async16(so, gp + (long)row * ld * 2);
    }
}

template<int EPI>
__device__ __forceinline__ void store_pair(long off, long c, float v0, float v1,
                                           const float* __restrict__ bias,
                                           const float* __restrict__ Res,
                                           float* __restrict__ C,
                                           bf16* __restrict__ Ch, bf16* __restrict__ Cl,
                                           float alpha) {
    v0 *= alpha; v1 *= alpha;
    if (EPI & 1) { v0 += bias[c]; v1 += bias[c + 1]; }
    if (EPI & 2) { v0 = fmaxf(v0, 0.f); v1 = fmaxf(v1, 0.f); }
    if (EPI & 4) {
        float2 rv = *(const float2*)(Res + off);
        v0 += rv.x; v1 += rv.y;
    }
    if (EPI & 8) {
        bf16 h0 = __float2bfloat16(v0), h1 = __float2bfloat16(v1);
        *(__nv_bfloat162*)(Ch + off) = __halves2bfloat162(h0, h1);
        *(__nv_bfloat162*)(Cl + off) = __halves2bfloat162(
            __float2bfloat16(v0 - __bfloat162float(h0)),
            __float2bfloat16(v1 - __bfloat162float(h1)));
    } else {
        *(float2*)(C + off) = make_float2(v0, v1);
    }
}

template<int EPI>
__global__ void __launch_bounds__(256, 1)
mmk(const bf16* __restrict__ Ah, const bf16* __restrict__ Al,
    const bf16* __restrict__ Bh, const bf16* __restrict__ Bl,
    const float* __restrict__ bias, const float* __restrict__ Res,
    float* __restrict__ C, bf16* __restrict__ Ch, bf16* __restrict__ Cl,
    int Kdim, int lda, int ldb, int ldc,
    int nh, long sA0, long sA1, long sB0, long sB1, long sC0, long sC1,
    float alpha)
{
    extern __shared__ __align__(1024) char smem[];
    const uint32_t sb = smem_u32(smem);
    const int tid = threadIdx.x;
    const int wid = tid >> 5, l = tid & 31;
    const int wm = wid >> 2, wn = wid & 3;     // 2 x 4 warp grid

    const int z = blockIdx.z;
    const long zb = z / nh, zh = z - zb * (long)nh;
    const long row0 = (long)blockIdx.y * 128;
    const long col0 = (long)blockIdx.x * 128;

    const long aoff = zb * sA0 + zh * sA1 + row0 * lda;
    const long boff = zb * sB0 + zh * sB1 + col0 * ldb;
    const bf16* pAh = Ah + aoff;
    const bf16* pAl = Al + aoff;
    const bf16* pBh = Bh + boff;
    const bf16* pBl = Bl + boff;

    float acc[4][4][4];
    #pragma unroll
    for (int i = 0; i < 4; i++)
        #pragma unroll
        for (int j = 0; j < 4; j++)
            #pragma unroll
            for (int r = 0; r < 4; r++) acc[i][j][r] = 0.0f;

    const int nchunk = Kdim >> 6;

    // prologue: prefetch 2 chunks
    #pragma unroll
    for (int s = 0; s < NST - 1; s++) {
        if (s < nchunk) {
            uint32_t st = sb + s * STAGEB;
            long k0 = (long)s << 6;
            tile_cp(st,             pAh + k0, lda, tid);
            tile_cp(st + TILEB,     pAl + k0, lda, tid);
            tile_cp(st + 2 * TILEB, pBh + k0, ldb, tid);
            tile_cp(st + 3 * TILEB, pBl + k0, ldb, tid);
        }
        cp_commit();
    }

    // per-lane ldmatrix base offsets
    const int ar = l & 15, asel = l >> 4, swa = l & 7;         // A rows
    const int br = ((l >> 4) << 3) + (l & 7), bsel = (l >> 3) & 1;
    const int swb = br & 7;

    for (int c = 0; c < nchunk; c++) {
        cp_wait<1>();
        __syncthreads();
        if (c + 2 < nchunk) {
            uint32_t st = sb + ((c + 2) % NST) * STAGEB;
            long k0 = (long)(c + 2) << 6;
            tile_cp(st,             pAh + k0, lda, tid);
            tile_cp(st + TILEB,     pAl + k0, lda, tid);
            tile_cp(st + 2 * TILEB, pBh + k0, ldb, tid);
            tile_cp(st + 3 * TILEB, pBl + k0, ldb, tid);
        }
        cp_commit();

        const uint32_t st = sb + (c % NST) * STAGEB;
        #pragma unroll
        for (int kp = 0; kp < 4; kp++) {
            uint32_t aH[4][4], aL[4][4], bH[4][2], bL[4][2];
            #pragma unroll
            for (int mt = 0; mt < 4; mt++) {
                int row = wm * 64 + mt * 16 + ar;
                uint32_t col = ((kp * 2 + asel) ^ swa) << 4;
                uint32_t ad = st + row * 128 + col;
                ldsm4(aH[mt][0], aH[mt][1], aH[mt][2], aH[mt][3], ad);
                ldsm4(aL[mt][0], aL[mt][1], aL[mt][2], aL[mt][3], ad + TILEB);
            }
            #pragma unroll
            for (int np = 0; np < 2; np++) {
                int row = wn * 32 + np * 16 + br;
                uint32_t col = ((kp * 2 + bsel) ^ swb) << 4;
                uint32_t bd = st + 2 * TILEB + row * 128 + col;
                ldsm4(bH[np*2][0], bH[np*2][1], bH[np*2+1][0], bH[np*2+1][1], bd);
                ldsm4(bL[np*2][0], bL[np*2][1], bL[np*2+1][0], bL[np*2+1][1], bd + TILEB);
            }
            #pragma unroll
            for (int mt = 0; mt < 4; mt++)
                #pragma unroll
                for (int nt = 0; nt < 4; nt++) {
                    mma16816(acc[mt][nt], aH[mt], bH[nt][0], bH[nt][1]);
                    mma16816(acc[mt][nt], aH[mt], bL[nt][0], bL[nt][1]);
                    mma16816(acc[mt][nt], aL[mt], bH[nt][0], bH[nt][1]);
                }
        }
        __syncthreads();
    }

    // ---------------- epilogue: direct register -> gmem
    const long Rw = row0 + wm * 64;
    const long Cw = col0 + wn * 32;
    const long base = zb * sC0 + zh * sC1;
    const int lr = l >> 2, lc = (l & 3) * 2;
    #pragma unroll
    for (int mt = 0; mt < 4; mt++) {
        long r0 = Rw + mt * 16 + lr;
        #pragma unroll
        for (int nt = 0; nt < 4; nt++) {
            long cc = Cw + nt * 8 + lc;
            store_pair<EPI>(base + r0 * ldc + cc, cc, acc[mt][nt][0], acc[mt][nt][1],
                            bias, Res, C, Ch, Cl, alpha);
            store_pair<EPI>(base + (r0 + 8) * ldc + cc, cc, acc[mt][nt][2], acc[mt][nt][3],
                            bias, Res, C, Ch, Cl, alpha);
        }
    }
}

// ---------------------------------------------------------------------------
// Launch
// ---------------------------------------------------------------------------
extern "C" void kernel_launch(void* const* d_in, const int* in_sizes, int n_in,
                              void* d_out, int out_size)
{
    const float* x      = (const float*)d_in[0];
    const float* conv_w = (const float*)d_in[1];
    const float* conv_b = (const float*)d_in[2];
    const float* w1 = (const float*)d_in[3];
    const float* b1 = (const float*)d_in[4];
    const float* w2 = (const float*)d_in[5];
    const float* b2 = (const float*)d_in[6];
    const float* ln_g = (const float*)d_in[7];
    const float* ln_b = (const float*)d_in[8];
    const float* wq = (const float*)d_in[9];
    const float* bq = (const float*)d_in[10];
    const float* wk = (const float*)d_in[11];
    const float* bk = (const float*)d_in[12];
    const float* wv = (const float*)d_in[13];
    const float* bv = (const float*)d_in[14];
    const float* wo = (const float*)d_in[15];
    const float* bo = (const float*)d_in[16];
    const float* wp = (const float*)d_in[17];
    const float* bp = (const float*)d_in[18];
    float* out = (float*)d_out;

    #define SYM(p, s) void* p; cudaGetSymbolAddress(&p, s)
    SYM(xah, g_xah); SYM(xal, g_xal);
    SYM(h1h, g_h1h); SYM(h1l, g_h1l);
    SYM(xreg, g_xreg);
    SYM(xnh, g_xnh); SYM(xnl, g_xnl);
    SYM(qh, g_qh); SYM(ql, g_ql); SYM(kh, g_kh); SYM(kl, g_kl);
    SYM(vv, g_v); SYM(vth, g_vth); SYM(vtl, g_vtl);
    SYM(ss, g_s); SYM(sh, g_sh); SYM(sl, g_sl);
    SYM(ch, g_ch); SYM(cl, g_cl);
    SYM(t1h, g_t1h); SYM(t1l, g_t1l);
    SYM(w1h, g_w1h); SYM(w1l, g_w1l);
    SYM(w2h, g_w2h); SYM(w2l, g_w2l);
    SYM(wqh, g_wqh); SYM(wql, g_wql);
    SYM(wkh, g_wkh); SYM(wkl, g_wkl);
    SYM(wvh, g_wvh); SYM(wvl, g_wvl);
    SYM(woh, g_woh); SYM(wol, g_wol);
    SYM(wph, g_wph); SYM(wpl, g_wpl);
    #undef SYM

    const int SMB = NST * STAGEB;   // 196608 bytes
    cudaFuncSetAttribute(mmk<11>, cudaFuncAttributeMaxDynamicSharedMemorySize, SMB);
    cudaFuncSetAttribute(mmk< 1>, cudaFuncAttributeMaxDynamicSharedMemorySize, SMB);
    cudaFuncSetAttribute(mmk< 9>, cudaFuncAttributeMaxDynamicSharedMemorySize, SMB);
    cudaFuncSetAttribute(mmk< 0>, cudaFuncAttributeMaxDynamicSharedMemorySize, SMB);
    cudaFuncSetAttribute(mmk< 5>, cudaFuncAttributeMaxDynamicSharedMemorySize, SMB);
    cudaFuncSetAttribute(mmk< 8>, cudaFuncAttributeMaxDynamicSharedMemorySize, SMB);

    const long MH = (long)Mc * Hc;
    const long MM = (long)Mc * Mc;
    const int  BMrows = Bc * Mc;  // 32768

    // 1. conv means, then affine + split into bf16 hi/lo
    means_k<<<1, 1024>>>(conv_w, conv_b);
    affine_k<<<(unsigned)(BMM / 4 / 256), 256>>>((const float4*)x, (bf16*)xah, (bf16*)xal);

    // 2. transpose + split all weights  [K,N] -> [N,K]
    wsplitT<<<dim3(Mc/32, Hc/32), dim3(32,8)>>>(w1, (bf16*)w1h, (bf16*)w1l, Mc, Hc);
    wsplitT<<<dim3(Hc/32, Hc/32), dim3(32,8)>>>(w2, (bf16*)w2h, (bf16*)w2l, Hc, Hc);
    wsplitT<<<dim3(Hc/32, Hc/32), dim3(32,8)>>>(wq, (bf16*)wqh, (bf16*)wql, Hc, Hc);
    wsplitT<<<dim3(Hc/32, Hc/32), dim3(32,8)>>>(wk, (bf16*)wkh, (bf16*)wkl, Hc, Hc);
    wsplitT<<<dim3(Hc/32, Hc/32), dim3(32,8)>>>(wv, (bf16*)wvh, (bf16*)wvl, Hc, Hc);
    wsplitT<<<dim3(Hc/32, Hc/32), dim3(32,8)>>>(wo, (bf16*)woh, (bf16*)wol, Hc, Hc);
    wsplitT<<<dim3(Hc/32, Hc/32), dim3(32,8)>>>(wp, (bf16*)wph, (bf16*)wpl, Hc, Hc);

    // 3. h1 = relu(xa @ w1 + b1) -> split
    mmk<11><<<dim3(Hc/128, BMrows/128, 1), 256, SMB>>>(
        (bf16*)xah, (bf16*)xal, (bf16*)w1h, (bf16*)w1l, b1, nullptr,
        nullptr, (bf16*)h1h, (bf16*)h1l,
        Mc, Mc, Mc, Hc, 1, 0,0,0,0,0,0, 1.0f);

    // 4. xreg = h1 @ w2 + b2 (fp32)
    mmk<1><<<dim3(Hc/128, BMrows/128, 1), 256, SMB>>>(
        (bf16*)h1h, (bf16*)h1l, (bf16*)w2h, (bf16*)w2l, b2, nullptr,
        (float*)xreg, nullptr, nullptr,
        Hc, Hc, Hc, Hc, 1, 0,0,0,0,0,0, 1.0f);

    // 5. layernorm -> split
    ln_k<<<BMrows, 256>>>((const float*)xreg, ln_g, ln_b, (bf16*)xnh, (bf16*)xnl);

    // 6. q, k (split), v (fp32)
    mmk<9><<<dim3(Hc/128, BMrows/128, 1), 256, SMB>>>(
        (bf16*)xnh, (bf16*)xnl, (bf16*)wqh, (bf16*)wql, bq, nullptr,
        nullptr, (bf16*)qh, (bf16*)ql, Hc, Hc, Hc, Hc, 1, 0,0,0,0,0,0, 1.0f);
    mmk<9><<<dim3(Hc/128, BMrows/128, 1), 256, SMB>>>(
        (bf16*)xnh, (bf16*)xnl, (bf16*)wkh, (bf16*)wkl, bk, nullptr,
        nullptr, (bf16*)kh, (bf16*)kl, Hc, Hc, Hc, Hc, 1, 0,0,0,0,0,0, 1.0f);
    mmk<1><<<dim3(Hc/128, BMrows/128, 1), 256, SMB>>>(
        (bf16*)xnh, (bf16*)xnl, (bf16*)wvh, (bf16*)wvl, bv, nullptr,
        (float*)vv, nullptr, nullptr, Hc, Hc, Hc, Hc, 1, 0,0,0,0,0,0, 1.0f);

    // 7. vT split  [B*NH, HD, M]
    vsplitT<<<dim3(Mc/32, HDc/32, Bc*NHc), dim3(32,8)>>>((const float*)vv, (bf16*)vth, (bf16*)vtl);

    // 8. scores = (Q @ K^T) / sqrt(HD)  (fp32), batched over b*h
    mmk<0><<<dim3(Mc/128, Mc/128, Bc*NHc), 256, SMB>>>(
        (bf16*)qh, (bf16*)ql, (bf16*)kh, (bf16*)kl, nullptr, nullptr,
        (float*)ss, nullptr, nullptr,
        HDc, Hc, Hc, Mc, NHc, MH, HDc, MH, HDc, (long)NHc*MM, MM,
        0.08838834764831845f);

    // 9. zero-diag + softmax -> split
    softmax_k<<<Bc*NHc*Mc, 128>>>((const float*)ss, (bf16*)sh, (bf16*)sl);

    // 10. ctx = attn @ V -> split, heads interleaved back into [B,M,H]
    mmk<8><<<dim3(HDc/128, Mc/128, Bc*NHc), 256, SMB>>>(
        (bf16*)sh, (bf16*)sl, (bf16*)vth, (bf16*)vtl, nullptr, nullptr,
        nullptr, (bf16*)ch, (bf16*)cl,
        Mc, Mc, Mc, Hc, NHc, (long)NHc*MM, MM,
        (long)NHc*HDc*Mc, (long)HDc*Mc, MH, HDc, 1.0f);

    // 11. t1 = ctx @ wo + bo -> split
    mmk<9><<<dim3(Hc/128, BMrows/128, 1), 256, SMB>>>(
        (bf16*)ch, (bf16*)cl, (bf16*)woh, (bf16*)wol, bo, nullptr,
        nullptr, (bf16*)t1h, (bf16*)t1l, Hc, Hc, Hc, Hc, 1, 0,0,0,0,0,0, 1.0f);

    // 12. out = t1 @ wp + bp + xreg (fp32)
    mmk<5><<<dim3(Hc/128, BMrows/128, 1), 256, SMB>>>(
        (bf16*)t1h, (bf16*)t1l, (bf16*)wph, (bf16*)wpl, bp, (const float*)xreg,
        out, nullptr, nullptr, Hc, Hc, Hc, Hc, 1, 0,0,0,0,0,0, 1.0f);
}

// round 5
// speedup vs baseline: 5.5008x; 1.8783x over previous
#include <cuda_runtime.h>
#include <cuda_bf16.h>
#include <cuda_fp16.h>
#include <cstdint>
#include <type_traits>

#define Bc  64
#define Mc  512
#define Hc  1024
#define NHc 8
#define HDc 128
#define EPSc 1e-5f

typedef __nv_bfloat16 bf16;
typedef __half        f16;

#define BMH ((size_t)Bc*Mc*Hc)
#define BMM ((size_t)Bc*Mc*Mc)
#define SMM ((size_t)Bc*NHc*Mc*Mc)

// ---------------------------------------------------------------------------
// Scratch (static device globals — allocation-free)
// ---------------------------------------------------------------------------
__device__ float g_mw, g_mb;
// MLP branch (bf16 3-term split)
__device__ bf16 g_xah[BMM], g_xal[BMM];
__device__ bf16 g_h1h[BMH], g_h1l[BMH];
__device__ float g_xreg[BMH];
__device__ bf16 g_w1h[(size_t)Hc*Mc],  g_w1l[(size_t)Hc*Mc];
__device__ bf16 g_w2h[(size_t)Hc*Hc],  g_w2l[(size_t)Hc*Hc];
// attention branch (fp16 single)
__device__ f16 g_xnh[BMH];
__device__ f16 g_qh[BMH], g_kh[BMH];
__device__ float g_v[BMH];
__device__ f16 g_vth[BMH];                        // [B*NH, 128, 512]
__device__ float g_s[SMM];
__device__ f16 g_sh[SMM];
__device__ f16 g_ch[BMH];
__device__ f16 g_t1h[BMH];
__device__ f16 g_wqh[(size_t)Hc*Hc];
__device__ f16 g_wkh[(size_t)Hc*Hc];
__device__ f16 g_wvh[(size_t)Hc*Hc];
__device__ f16 g_woh[(size_t)Hc*Hc];
__device__ f16 g_wph[(size_t)Hc*Hc];

// ---------------------------------------------------------------------------
// type traits
// ---------------------------------------------------------------------------
template<typename T> struct TT;
template<> struct TT<bf16> {
    using T2 = __nv_bfloat162;
    static __device__ __forceinline__ bf16 c(float v) { return __float2bfloat16(v); }
    static __device__ __forceinline__ float f(bf16 v) { return __bfloat162float(v); }
    static __device__ __forceinline__ T2 pack(bf16 a, bf16 b) { return __halves2bfloat162(a, b); }
};
template<> struct TT<f16> {
    using T2 = __half2;
    static __device__ __forceinline__ f16 c(float v) { return __float2half(v); }
    static __device__ __forceinline__ float f(f16 v) { return __half2float(v); }
    static __device__ __forceinline__ T2 pack(f16 a, f16 b) { return __halves2half2(a, b); }
};

// ---------------------------------------------------------------------------
// PTX helpers (baseline PTX only — no tcgen05 on compute_103)
// ---------------------------------------------------------------------------
__device__ __forceinline__ uint32_t smem_u32(const void* p) {
    uint32_t a;
    asm("{ .reg .u64 t; cvta.to.shared.u64 t, %1; cvt.u32.u64 %0, t; }"
        : "=r"(a) : "l"(p));
    return a;
}

__device__ __forceinline__ void cp_async16(uint32_t saddr, const void* gaddr) {
    asm volatile("cp.async.cg.shared.global [%0], [%1], 16;\n"
                 :: "r"(saddr), "l"(gaddr));
}
__device__ __forceinline__ void cp_commit() {
    asm volatile("cp.async.commit_group;\n" ::: "memory");
}
template<int N>
__device__ __forceinline__ void cp_wait() {
    asm volatile("cp.async.wait_group %0;\n" :: "n"(N) : "memory");
}

__device__ __forceinline__ void ldsm4(uint32_t& r0, uint32_t& r1, uint32_t& r2, uint32_t& r3,
                                      uint32_t addr) {
    asm volatile("ldmatrix.sync.aligned.m8n8.x4.shared.b16 {%0,%1,%2,%3}, [%4];"
                 : "=r"(r0), "=r"(r1), "=r"(r2), "=r"(r3) : "r"(addr));
}

template<typename T>
__device__ __forceinline__ void mma16816(float* c, const uint32_t* a, uint32_t b0, uint32_t b1) {
    if constexpr (std::is_same_v<T, bf16>) {
        asm volatile("mma.sync.aligned.m16n8k16.row.col.f32.bf16.bf16.f32 "
                     "{%0,%1,%2,%3}, {%4,%5,%6,%7}, {%8,%9}, {%0,%1,%2,%3};"
                     : "+f"(c[0]), "+f"(c[1]), "+f"(c[2]), "+f"(c[3])
                     : "r"(a[0]), "r"(a[1]), "r"(a[2]), "r"(a[3]), "r"(b0), "r"(b1));
    } else {
        asm volatile("mma.sync.aligned.m16n8k16.row.col.f32.f16.f16.f32 "
                     "{%0,%1,%2,%3}, {%4,%5,%6,%7}, {%8,%9}, {%0,%1,%2,%3};"
                     : "+f"(c[0]), "+f"(c[1]), "+f"(c[2]), "+f"(c[3])
                     : "r"(a[0]), "r"(a[1]), "r"(a[2]), "r"(a[3]), "r"(b0), "r"(b1));
    }
}

// ---------------------------------------------------------------------------
// small kernels
// ---------------------------------------------------------------------------
__global__ void means_k(const float* __restrict__ w, const float* __restrict__ b) {
    __shared__ float sw[32], sb[32];
    int t = threadIdx.x;
    float vw = w[t], vb = b[t];
    #pragma unroll
    for (int o = 16; o > 0; o >>= 1) {
        vw += __shfl_down_sync(0xffffffffu, vw, o);
        vb += __shfl_down_sync(0xffffffffu, vb, o);
    }
    if ((t & 31) == 0) { sw[t >> 5] = vw; sb[t >> 5] = vb; }
    __syncthreads();
    if (t < 32) {
        vw = sw[t]; vb = sb[t];
        #pragma unroll
        for (int o = 16; o > 0; o >>= 1) {
            vw += __shfl_down_sync(0xffffffffu, vw, o);
            vb += __shfl_down_sync(0xffffffffu, vb, o);
        }
        if (t == 0) { g_mw = vw / (float)Hc; g_mb = vb / (float)Hc; }
    }
}

__device__ __forceinline__ void bsplit_store4(bf16* __restrict__ ph, bf16* __restrict__ pl,
                                              float v0, float v1, float v2, float v3) {
    bf16 h0 = __float2bfloat16(v0), h1 = __float2bfloat16(v1);
    bf16 h2 = __float2bfloat16(v2), h3 = __float2bfloat16(v3);
    ((__nv_bfloat162*)ph)[0] = __halves2bfloat162(h0, h1);
    ((__nv_bfloat162*)ph)[1] = __halves2bfloat162(h2, h3);
    ((__nv_bfloat162*)pl)[0] = __halves2bfloat162(
        __float2bfloat16(v0 - __bfloat162float(h0)), __float2bfloat16(v1 - __bfloat162float(h1)));
    ((__nv_bfloat162*)pl)[1] = __halves2bfloat162(
        __float2bfloat16(v2 - __bfloat162float(h2)), __float2bfloat16(v3 - __bfloat162float(h3)));
}

__global__ void affine_k(const float4* __restrict__ x, bf16* __restrict__ xh, bf16* __restrict__ xl) {
    long i = (long)blockIdx.x * blockDim.x + threadIdx.x;
    float a = 1.0f + g_mw, c = g_mb;
    float4 v = x[i];
    bsplit_store4(xh + i * 4, xl + i * 4, v.x * a + c, v.y * a + c, v.z * a + c, v.w * a + c);
}

// W [K,N] fp32 -> WT hi/lo [N,K] bf16  (MLP weights)
__global__ void wsplitT(const float* __restrict__ W, bf16* __restrict__ th, bf16* __restrict__ tl,
                        int K, int N) {
    __shared__ float t[32][33];
    int k0 = blockIdx.x * 32, n0 = blockIdx.y * 32;
    int tx = threadIdx.x, ty = threadIdx.y;
    #pragma unroll
    for (int i = ty; i < 32; i += 8)
        t[i][tx] = W[(long)(k0 + i) * N + n0 + tx];
    __syncthreads();
    #pragma unroll
    for (int i = ty; i < 32; i += 8) {
        float v = t[tx][i];
        bf16 h = __float2bfloat16(v);
        long o = (long)(n0 + i) * K + k0 + tx;
        th[o] = h;
        tl[o] = __float2bfloat16(v - __bfloat162float(h));
    }
}

// W [K,N] fp32 -> WT fp16 [N,K]  (attention weights)
__global__ void wsplit1(const float* __restrict__ W, f16* __restrict__ th, int K, int N) {
    __shared__ float t[32][33];
    int k0 = blockIdx.x * 32, n0 = blockIdx.y * 32;
    int tx = threadIdx.x, ty = threadIdx.y;
    #pragma unroll
    for (int i = ty; i < 32; i += 8)
        t[i][tx] = W[(long)(k0 + i) * N + n0 + tx];
    __syncthreads();
    #pragma unroll
    for (int i = ty; i < 32; i += 8)
        th[(long)(n0 + i) * K + k0 + tx] = __float2half(t[tx][i]);
}

// v fp32 [B*M, H] -> vT fp16 [(B*NH), HD, M]
__global__ void vsplitT(const float* __restrict__ v, f16* __restrict__ th) {
    __shared__ float t[32][33];
    int z = blockIdx.z, zb = z >> 3, zh = z & 7;
    int m0 = blockIdx.x * 32, d0 = blockIdx.y * 32;
    int tx = threadIdx.x, ty = threadIdx.y;
    #pragma unroll
    for (int i = ty; i < 32; i += 8)
        t[i][tx] = v[((long)zb * Mc + m0 + i) * Hc + zh * HDc + d0 + tx];
    __syncthreads();
    #pragma unroll
    for (int i = ty; i < 32; i += 8)
        th[((long)z * HDc + d0 + i) * Mc + m0 + tx] = __float2half(t[tx][i]);
}

__global__ void ln_k(const float* __restrict__ in, const float* __restrict__ g,
                     const float* __restrict__ be, f16* __restrict__ oh) {
    long row = blockIdx.x;
    const float4* p = (const float4*)(in + row * Hc);
    int t = threadIdx.x;
    float4 v = p[t];
    float s  = v.x + v.y + v.z + v.w;
    float s2 = v.x * v.x + v.y * v.y + v.z * v.z + v.w * v.w;
    __shared__ float ss[8], ss2[8];
    #pragma unroll
    for (int of = 16; of > 0; of >>= 1) {
        s  += __shfl_down_sync(0xffffffffu, s, of);
        s2 += __shfl_down_sync(0xffffffffu, s2, of);
    }
    if ((t & 31) == 0) { ss[t >> 5] = s; ss2[t >> 5] = s2; }
    __syncthreads();
    __shared__ float mu_s, ri_s;
    if (t == 0) {
        float a = 0.f, b2 = 0.f;
        #pragma unroll
        for (int i = 0; i < 8; i++) { a += ss[i]; b2 += ss2[i]; }
        float mu = a / (float)Hc;
        mu_s = mu;
        ri_s = rsqrtf(b2 / (float)Hc - mu * mu + EPSc);
    }
    __syncthreads();
    float mu = mu_s, ri = ri_s;
    float4 gv = ((const float4*)g)[t];
    float4 bv = ((const float4*)be)[t];
    long o = row * Hc + t * 4;
    ((__half2*)(oh + o))[0] = __halves2half2(
        __float2half((v.x - mu) * ri * gv.x + bv.x), __float2half((v.y - mu) * ri * gv.y + bv.y));
    ((__half2*)(oh + o))[1] = __halves2half2(
        __float2half((v.z - mu) * ri * gv.z + bv.z), __float2half((v.w - mu) * ri * gv.w + bv.w));
}

__global__ void softmax_k(const float* __restrict__ s, f16* __restrict__ sh) {
    long row = blockIdx.x;
    int  qi  = (int)(row & (Mc - 1));
    const float4* p = (const float4*)(s + row * Mc);
    int t = threadIdx.x;
    float4 v = p[t];
    int c0 = t * 4;
    if (qi >= c0 && qi < c0 + 4) ((float*)&v)[qi - c0] = 0.0f;

    float m = fmaxf(fmaxf(v.x, v.y), fmaxf(v.z, v.w));
    __shared__ float sm[4];
    #pragma unroll
    for (int of = 16; of > 0; of >>= 1) m = fmaxf(m, __shfl_xor_sync(0xffffffffu, m, of));
    if ((t & 31) == 0) sm[t >> 5] = m;
    __syncthreads();
    m = fmaxf(fmaxf(sm[0], sm[1]), fmaxf(sm[2], sm[3]));

    v.x = expf(v.x - m); v.y = expf(v.y - m);
    v.z = expf(v.z - m); v.w = expf(v.w - m);
    float su = v.x + v.y + v.z + v.w;
    __shared__ float ssum[4];
    #pragma unroll
    for (int of = 16; of > 0; of >>= 1) su += __shfl_xor_sync(0xffffffffu, su, of);
    if ((t & 31) == 0) ssum[t >> 5] = su;
    __syncthreads();
    su = ssum[0] + ssum[1] + ssum[2] + ssum[3];
    float r = 1.0f / su;
    long o = row * Mc + t * 4;
    ((__half2*)(sh + o))[0] = __halves2half2(__float2half(v.x * r), __float2half(v.y * r));
    ((__half2*)(sh + o))[1] = __halves2half2(__float2half(v.z * r), __float2half(v.w * r));
}

// ---------------------------------------------------------------------------
// mma.sync GEMM: C[M,N] = alpha * (A @ B^T) (+bias)(relu)(+res)
//   T = bf16 or fp16 (element type of A/B and T-outputs)
//   SPLIT=true : 3-term hi/lo emulation (Ah,Al,Bh,Bl)
//   SPLIT=false: single (Ah, Bh only)
//   OUT: 0 = fp32 C, 1 = T Ch, 2 = T split Ch+Cl
//   EPI bits: 1=bias, 2=relu, 4=residual
//   BM=BN=128, BK=64, 256 thr = 8 warps (2x4), warp tile 64x32, 3 stages.
// ---------------------------------------------------------------------------
#define NST 3
#define TILEB 16384                 // one 128x64 16-bit tile

template<typename T>
__device__ __forceinline__ void tile_cp(uint32_t sm, const T* __restrict__ g, long ld, int tid) {
    int r = tid >> 3;
    int c16 = tid & 7;
    const char* gp = (const char*)(g + c16 * 8);
    #pragma unroll
    for (int i = 0; i < 4; i++) {
        int row = r + i * 32;
        uint32_t so = sm + row * 128 + ((c16 ^ (row & 7)) << 4);
        cp_async16(so, gp + (long)row * ld * 2);
    }
}

template<typename T, int OUT, int EPI>
__device__ __forceinline__ void store_pair(long off, long c, float v0, float v1,
                                           const float* __restrict__ bias,
                                           const float* __restrict__ Res,
                                           float* __restrict__ C,
                                           T* __restrict__ Ch, T* __restrict__ Cl,
                                           float alpha) {
    v0 *= alpha; v1 *= alpha;
    if (EPI & 1) { v0 += bias[c]; v1 += bias[c + 1]; }
    if (EPI & 2) { v0 = fmaxf(v0, 0.f); v1 = fmaxf(v1, 0.f); }
    if (EPI & 4) {
        float2 rv = *(const float2*)(Res + off);
        v0 += rv.x; v1 += rv.y;
    }
    if (OUT == 0) {
        *(float2*)(C + off) = make_float2(v0, v1);
    } else {
        T h0 = TT<T>::c(v0), h1 = TT<T>::c(v1);
        *(typename TT<T>::T2*)(Ch + off) = TT<T>::pack(h0, h1);
        if (OUT == 2) {
            *(typename TT<T>::T2*)(Cl + off) = TT<T>::pack(
                TT<T>::c(v0 - TT<T>::f(h0)), TT<T>::c(v1 - TT<T>::f(h1)));
        }
    }
}

template<typename T, bool SPLIT, int OUT, int EPI>
__global__ void __launch_bounds__(256, SPLIT ? 1 : 2)
mmk(const T* __restrict__ Ah, const T* __restrict__ Al,
    const T* __restrict__ Bh, const T* __restrict__ Bl,
    const float* __restrict__ bias, const float* __restrict__ Res,
    float* __restrict__ C, T* __restrict__ Ch, T* __restrict__ Cl,
    int Kdim, int lda, int ldb, int ldc,
    int nh, long sA0, long sA1, long sB0, long sB1, long sC0, long sC1,
    float alpha)
{
    extern __shared__ __align__(1024) char smem[];
    constexpr int NTILE = SPLIT ? 4 : 2;
    constexpr int STAGEB = NTILE * TILEB;
    constexpr int BOFF = SPLIT ? 2 * TILEB : TILEB;

    const uint32_t sb = smem_u32(smem);
    const int tid = threadIdx.x;
    const int wid = tid >> 5, l = tid & 31;
    const int wm = wid >> 2, wn = wid & 3;

    const int z = blockIdx.z;
    const long zb = z / nh, zh = z - zb * (long)nh;
    const long row0 = (long)blockIdx.y * 128;
    const long col0 = (long)blockIdx.x * 128;

    const long aoff = zb * sA0 + zh * sA1 + row0 * lda;
    const long boff = zb * sB0 + zh * sB1 + col0 * ldb;
    const T* pAh = Ah + aoff;
    const T* pAl = SPLIT ? (Al + aoff) : nullptr;
    const T* pBh = Bh + boff;
    const T* pBl = SPLIT ? (Bl + boff) : nullptr;

    float acc[4][4][4];
    #pragma unroll
    for (int i = 0; i < 4; i++)
        #pragma unroll
        for (int j = 0; j < 4; j++)
            #pragma unroll
            for (int r = 0; r < 4; r++) acc[i][j][r] = 0.0f;

    const int nchunk = Kdim >> 6;

    #pragma unroll
    for (int s = 0; s < NST - 1; s++) {
        if (s < nchunk) {
            uint32_t st = sb + s * STAGEB;
            long k0 = (long)s << 6;
            tile_cp(st,        pAh + k0, lda, tid);
            if (SPLIT) tile_cp(st + TILEB, pAl + k0, lda, tid);
            tile_cp(st + BOFF, pBh + k0, ldb, tid);
            if (SPLIT) tile_cp(st + BOFF + TILEB, pBl + k0, ldb, tid);
        }
        cp_commit();
    }

    const int ar = l & 15, asel = l >> 4, swa = l & 7;
    const int br = ((l >> 4) << 3) + (l & 7), bsel = (l >> 3) & 1;
    const int swb = br & 7;

    for (int c = 0; c < nchunk; c++) {
        cp_wait<1>();
        __syncthreads();
        if (c + 2 < nchunk) {
            uint32_t st = sb + ((c + 2) % NST) * STAGEB;
            long k0 = (long)(c + 2) << 6;
            tile_cp(st,        pAh + k0, lda, tid);
            if (SPLIT) tile_cp(st + TILEB, pAl + k0, lda, tid);
            tile_cp(st + BOFF, pBh + k0, ldb, tid);
            if (SPLIT) tile_cp(st + BOFF + TILEB, pBl + k0, ldb, tid);
        }
        cp_commit();

        const uint32_t st = sb + (c % NST) * STAGEB;
        #pragma unroll
        for (int kp = 0; kp < 4; kp++) {
            uint32_t aH[4][4], aL[4][4], bH[4][2], bL[4][2];
            #pragma unroll
            for (int mt = 0; mt < 4; mt++) {
                int row = wm * 64 + mt * 16 + ar;
                uint32_t col = ((kp * 2 + asel) ^ swa) << 4;
                uint32_t ad = st + row * 128 + col;
                ldsm4(aH[mt][0], aH[mt][1], aH[mt][2], aH[mt][3], ad);
                if (SPLIT) ldsm4(aL[mt][0], aL[mt][1], aL[mt][2], aL[mt][3], ad + TILEB);
            }
            #pragma unroll
            for (int np = 0; np < 2; np++) {
                int row = wn * 32 + np * 16 + br;
                uint32_t col = ((kp * 2 + bsel) ^ swb) << 4;
                uint32_t bd = st + BOFF + row * 128 + col;
                ldsm4(bH[np*2][0], bH[np*2][1], bH[np*2+1][0], bH[np*2+1][1], bd);
                if (SPLIT) ldsm4(bL[np*2][0], bL[np*2][1], bL[np*2+1][0], bL[np*2+1][1], bd + TILEB);
            }
            #pragma unroll
            for (int mt = 0; mt < 4; mt++)
                #pragma unroll
                for (int nt = 0; nt < 4; nt++) {
                    mma16816<T>(acc[mt][nt], aH[mt], bH[nt][0], bH[nt][1]);
                    if (SPLIT) {
                        mma16816<T>(acc[mt][nt], aH[mt], bL[nt][0], bL[nt][1]);
                        mma16816<T>(acc[mt][nt], aL[mt], bH[nt][0], bH[nt][1]);
                    }
                }
        }
        __syncthreads();
    }

    const long Rw = row0 + wm * 64;
    const long Cw = col0 + wn * 32;
    const long base = zb * sC0 + zh * sC1;
    const int lr = l >> 2, lc = (l & 3) * 2;
    #pragma unroll
    for (int mt = 0; mt < 4; mt++) {
        long r0 = Rw + mt * 16 + lr;
        #pragma unroll
        for (int nt = 0; nt < 4; nt++) {
            long cc = Cw + nt * 8 + lc;
            store_pair<T, OUT, EPI>(base + r0 * ldc + cc, cc, acc[mt][nt][0], acc[mt][nt][1],
                                    bias, Res, C, Ch, Cl, alpha);
            store_pair<T, OUT, EPI>(base + (r0 + 8) * ldc + cc, cc, acc[mt][nt][2], acc[mt][nt][3],
                                    bias, Res, C, Ch, Cl, alpha);
        }
    }
}

// ---------------------------------------------------------------------------
// Launch
// ---------------------------------------------------------------------------
extern "C" void kernel_launch(void* const* d_in, const int* in_sizes, int n_in,
                              void* d_out, int out_size)
{
    const float* x      = (const float*)d_in[0];
    const float* conv_w = (const float*)d_in[1];
    const float* conv_b = (const float*)d_in[2];
    const float* w1 = (const float*)d_in[3];
    const float* b1 = (const float*)d_in[4];
    const float* w2 = (const float*)d_in[5];
    const float* b2 = (const float*)d_in[6];
    const float* ln_g = (const float*)d_in[7];
    const float* ln_b = (const float*)d_in[8];
    const float* wq = (const float*)d_in[9];
    const float* bq = (const float*)d_in[10];
    const float* wk = (const float*)d_in[11];
    const float* bk = (const float*)d_in[12];
    const float* wv = (const float*)d_in[13];
    const float* bv = (const float*)d_in[14];
    const float* wo = (const float*)d_in[15];
    const float* bo = (const float*)d_in[16];
    const float* wp = (const float*)d_in[17];
    const float* bp = (const float*)d_in[18];
    float* out = (float*)d_out;

    #define SYM(p, s) void* p; cudaGetSymbolAddress(&p, s)
    SYM(xah, g_xah); SYM(xal, g_xal);
    SYM(h1h, g_h1h); SYM(h1l, g_h1l);
    SYM(xreg, g_xreg);
    SYM(xnh, g_xnh);
    SYM(qh, g_qh); SYM(kh, g_kh);
    SYM(vv, g_v); SYM(vth, g_vth);
    SYM(ss, g_s); SYM(sh, g_sh);
    SYM(ch, g_ch);
    SYM(t1h, g_t1h);
    SYM(w1h, g_w1h); SYM(w1l, g_w1l);
    SYM(w2h, g_w2h); SYM(w2l, g_w2l);
    SYM(wqh, g_wqh); SYM(wkh, g_wkh); SYM(wvh, g_wvh);
    SYM(woh, g_woh); SYM(wph, g_wph);
    #undef SYM

    const int SMB_S = NST * 4 * TILEB;   // 196608 (split)
    const int SMB_1 = NST * 2 * TILEB;   //  98304 (single)
    cudaFuncSetAttribute(mmk<bf16,true, 2,3>, cudaFuncAttributeMaxDynamicSharedMemorySize, SMB_S);
    cudaFuncSetAttribute(mmk<bf16,true, 0,1>, cudaFuncAttributeMaxDynamicSharedMemorySize, SMB_S);
    cudaFuncSetAttribute(mmk<f16,false,1,1>, cudaFuncAttributeMaxDynamicSharedMemorySize, SMB_1);
    cudaFuncSetAttribute(mmk<f16,false,0,1>, cudaFuncAttributeMaxDynamicSharedMemorySize, SMB_1);
    cudaFuncSetAttribute(mmk<f16,false,0,0>, cudaFuncAttributeMaxDynamicSharedMemorySize, SMB_1);
    cudaFuncSetAttribute(mmk<f16,false,1,0>, cudaFuncAttributeMaxDynamicSharedMemorySize, SMB_1);
    cudaFuncSetAttribute(mmk<f16,false,0,5>, cudaFuncAttributeMaxDynamicSharedMemorySize, SMB_1);

    const long MH = (long)Mc * Hc;
    const long MM = (long)Mc * Mc;
    const int  BMrows = Bc * Mc;  // 32768

    // 1. conv means, affine + bf16 split
    means_k<<<1, 1024>>>(conv_w, conv_b);
    affine_k<<<(unsigned)(BMM / 4 / 256), 256>>>((const float4*)x, (bf16*)xah, (bf16*)xal);

    // 2. weight transposes: bf16 split for MLP, fp16 for attention
    wsplitT<<<dim3(Mc/32, Hc/32), dim3(32,8)>>>(w1, (bf16*)w1h, (bf16*)w1l, Mc, Hc);
    wsplitT<<<dim3(Hc/32, Hc/32), dim3(32,8)>>>(w2, (bf16*)w2h, (bf16*)w2l, Hc, Hc);
    wsplit1<<<dim3(Hc/32, Hc/32), dim3(32,8)>>>(wq, (f16*)wqh, Hc, Hc);
    wsplit1<<<dim3(Hc/32, Hc/32), dim3(32,8)>>>(wk, (f16*)wkh, Hc, Hc);
    wsplit1<<<dim3(Hc/32, Hc/32), dim3(32,8)>>>(wv, (f16*)wvh, Hc, Hc);
    wsplit1<<<dim3(Hc/32, Hc/32), dim3(32,8)>>>(wo, (f16*)woh, Hc, Hc);
    wsplit1<<<dim3(Hc/32, Hc/32), dim3(32,8)>>>(wp, (f16*)wph, Hc, Hc);

    // 3. h1 = relu(xa @ w1 + b1) -> bf16 split (3-term)
    mmk<bf16,true,2,3><<<dim3(Hc/128, BMrows/128, 1), 256, SMB_S>>>(
        (bf16*)xah, (bf16*)xal, (bf16*)w1h, (bf16*)w1l, b1, nullptr,
        nullptr, (bf16*)h1h, (bf16*)h1l,
        Mc, Mc, Mc, Hc, 1, 0,0,0,0,0,0, 1.0f);

    // 4. xreg = h1 @ w2 + b2 (fp32)  (3-term)
    mmk<bf16,true,0,1><<<dim3(Hc/128, BMrows/128, 1), 256, SMB_S>>>(
        (bf16*)h1h, (bf16*)h1l, (bf16*)w2h, (bf16*)w2l, b2, nullptr,
        (float*)xreg, nullptr, nullptr,
        Hc, Hc, Hc, Hc, 1, 0,0,0,0,0,0, 1.0f);

    // 5. layernorm -> fp16
    ln_k<<<BMrows, 256>>>((const float*)xreg, ln_g, ln_b, (f16*)xnh);

    // 6. q, k (fp16), v (fp32) — single-pass fp16
    mmk<f16,false,1,1><<<dim3(Hc/128, BMrows/128, 1), 256, SMB_1>>>(
        (f16*)xnh, nullptr, (f16*)wqh, nullptr, bq, nullptr,
        nullptr, (f16*)qh, nullptr, Hc, Hc, Hc, Hc, 1, 0,0,0,0,0,0, 1.0f);
    mmk<f16,false,1,1><<<dim3(Hc/128, BMrows/128, 1), 256, SMB_1>>>(
        (f16*)xnh, nullptr, (f16*)wkh, nullptr, bk, nullptr,
        nullptr, (f16*)kh, nullptr, Hc, Hc, Hc, Hc, 1, 0,0,0,0,0,0, 1.0f);
    mmk<f16,false,0,1><<<dim3(Hc/128, BMrows/128, 1), 256, SMB_1>>>(
        (f16*)xnh, nullptr, (f16*)wvh, nullptr, bv, nullptr,
        (float*)vv, nullptr, nullptr, Hc, Hc, Hc, Hc, 1, 0,0,0,0,0,0, 1.0f);

    // 7. vT fp16  [B*NH, HD, M]
    vsplitT<<<dim3(Mc/32, HDc/32, Bc*NHc), dim3(32,8)>>>((const float*)vv, (f16*)vth);

    // 8. scores = (Q @ K^T) / sqrt(HD)  (fp32) — single-pass fp16
    mmk<f16,false,0,0><<<dim3(Mc/128, Mc/128, Bc*NHc), 256, SMB_1>>>(
        (f16*)qh, nullptr, (f16*)kh, nullptr, nullptr, nullptr,
        (float*)ss, nullptr, nullptr,
        HDc, Hc, Hc, Mc, NHc, MH, HDc, MH, HDc, (long)NHc*MM, MM,
        0.08838834764831845f);

    // 9. zero-diag + softmax -> fp16
    softmax_k<<<Bc*NHc*Mc, 128>>>((const float*)ss, (f16*)sh);

    // 10. ctx = attn @ V -> fp16, heads interleaved into [B,M,H]
    mmk<f16,false,1,0><<<dim3(HDc/128, Mc/128, Bc*NHc), 256, SMB_1>>>(
        (f16*)sh, nullptr, (f16*)vth, nullptr, nullptr, nullptr,
        nullptr, (f16*)ch, nullptr,
        Mc, Mc, Mc, Hc, NHc, (long)NHc*MM, MM,
        (long)NHc*HDc*Mc, (long)HDc*Mc, MH, HDc, 1.0f);

    // 11. t1 = ctx @ wo + bo -> fp16
    mmk<f16,false,1,1><<<dim3(Hc/128, BMrows/128, 1), 256, SMB_1>>>(
        (f16*)ch, nullptr, (f16*)woh, nullptr, bo, nullptr,
        nullptr, (f16*)t1h, nullptr, Hc, Hc, Hc, Hc, 1, 0,0,0,0,0,0, 1.0f);

    // 12. out = t1 @ wp + bp + xreg (fp32)
    mmk<f16,false,0,5><<<dim3(Hc/128, BMrows/128, 1), 256, SMB_1>>>(
        (f16*)t1h, nullptr, (f16*)wph, nullptr, bp, (const float*)xreg,
        out, nullptr, nullptr, Hc, Hc, Hc, Hc, 1, 0,0,0,0,0,0, 1.0f);
}

// round 7
// speedup vs baseline: 6.0609x; 1.1018x over previous
#include <cuda_runtime.h>
#include <cuda_bf16.h>
#include <cuda_fp16.h>
#include <cstdint>
#include <type_traits>

#define Bc  64
#define Mc  512
#define Hc  1024
#define NHc 8
#define HDc 128
#define EPSc 1e-5f

typedef __nv_bfloat16 bf16;
typedef __half        f16;

#define BMH ((size_t)Bc*Mc*Hc)
#define BMM ((size_t)Bc*Mc*Mc)

// ---------------------------------------------------------------------------
// Scratch (static device globals — allocation-free)
// ---------------------------------------------------------------------------
__device__ float g_mw, g_mb;
// MLP branch (bf16 3-term split)
__device__ bf16 g_xah[BMM], g_xal[BMM];
__device__ bf16 g_h1h[BMH], g_h1l[BMH];
__device__ float g_xreg[BMH];
__device__ bf16 g_w1h[(size_t)Hc*Mc],  g_w1l[(size_t)Hc*Mc];
__device__ bf16 g_w2h[(size_t)Hc*Hc],  g_w2l[(size_t)Hc*Hc];
// attention branch (fp16 single)
__device__ f16 g_xnh[BMH];
__device__ f16 g_qkv[(size_t)Bc*Mc*3*Hc];         // [B*M, 3072] = q|k|v
__device__ f16 g_vth[BMH];                        // [B*NH, 128, 512]
__device__ f16 g_ch[BMH];
__device__ f16 g_t1h[BMH];
__device__ f16 g_wqkv[(size_t)3*Hc*Hc];           // [3072, 1024]
__device__ float g_bqkv[3*Hc];
__device__ f16 g_woh[(size_t)Hc*Hc];
__device__ f16 g_wph[(size_t)Hc*Hc];

// ---------------------------------------------------------------------------
// type traits
// ---------------------------------------------------------------------------
template<typename T> struct TT;
template<> struct TT<bf16> {
    using T2 = __nv_bfloat162;
    static __device__ __forceinline__ bf16 c(float v) { return __float2bfloat16(v); }
    static __device__ __forceinline__ float f(bf16 v) { return __bfloat162float(v); }
    static __device__ __forceinline__ T2 pack(bf16 a, bf16 b) { return __halves2bfloat162(a, b); }
};
template<> struct TT<f16> {
    using T2 = __half2;
    static __device__ __forceinline__ f16 c(float v) { return __float2half(v); }
    static __device__ __forceinline__ float f(f16 v) { return __half2float(v); }
    static __device__ __forceinline__ T2 pack(f16 a, f16 b) { return __halves2half2(a, b); }
};

// ---------------------------------------------------------------------------
// PTX helpers (baseline PTX only — no tcgen05 on compute_103)
// ---------------------------------------------------------------------------
__device__ __forceinline__ uint32_t smem_u32(const void* p) {
    uint32_t a;
    asm("{ .reg .u64 t; cvta.to.shared.u64 t, %1; cvt.u32.u64 %0, t; }"
        : "=r"(a) : "l"(p));
    return a;
}

// pack two fp32 -> one u32 holding {hi:f16(h), lo:f16(l)}
__device__ __forceinline__ uint32_t f2h2(float lo, float hi) {
    uint32_t r;
    asm("cvt.rn.f16x2.f32 %0, %1, %2;" : "=r"(r) : "f"(hi), "f"(lo));
    return r;
}

__device__ __forceinline__ void cp_async16(uint32_t saddr, const void* gaddr) {
    asm volatile("cp.async.cg.shared.global [%0], [%1], 16;\n"
                 :: "r"(saddr), "l"(gaddr));
}
__device__ __forceinline__ void cp_commit() {
    asm volatile("cp.async.commit_group;\n" ::: "memory");
}
template<int N>
__device__ __forceinline__ void cp_wait() {
    asm volatile("cp.async.wait_group %0;\n" :: "n"(N) : "memory");
}

__device__ __forceinline__ void ldsm4(uint32_t& r0, uint32_t& r1, uint32_t& r2, uint32_t& r3,
                                      uint32_t addr) {
    asm volatile("ldmatrix.sync.aligned.m8n8.x4.shared.b16 {%0,%1,%2,%3}, [%4];"
                 : "=r"(r0), "=r"(r1), "=r"(r2), "=r"(r3) : "r"(addr));
}

template<typename T>
__device__ __forceinline__ void mma16816(float* c, const uint32_t* a, uint32_t b0, uint32_t b1) {
    if constexpr (std::is_same_v<T, bf16>) {
        asm volatile("mma.sync.aligned.m16n8k16.row.col.f32.bf16.bf16.f32 "
                     "{%0,%1,%2,%3}, {%4,%5,%6,%7}, {%8,%9}, {%0,%1,%2,%3};"
                     : "+f"(c[0]), "+f"(c[1]), "+f"(c[2]), "+f"(c[3])
                     : "r"(a[0]), "r"(a[1]), "r"(a[2]), "r"(a[3]), "r"(b0), "r"(b1));
    } else {
        asm volatile("mma.sync.aligned.m16n8k16.row.col.f32.f16.f16.f32 "
                     "{%0,%1,%2,%3}, {%4,%5,%6,%7}, {%8,%9}, {%0,%1,%2,%3};"
                     : "+f"(c[0]), "+f"(c[1]), "+f"(c[2]), "+f"(c[3])
                     : "r"(a[0]), "r"(a[1]), "r"(a[2]), "r"(a[3]), "r"(b0), "r"(b1));
    }
}

// ---------------------------------------------------------------------------
// small kernels
// ---------------------------------------------------------------------------
__global__ void means_k(const float* __restrict__ w, const float* __restrict__ b) {
    __shared__ float sw[32], sb[32];
    int t = threadIdx.x;
    float vw = w[t], vb = b[t];
    #pragma unroll
    for (int o = 16; o > 0; o >>= 1) {
        vw += __shfl_down_sync(0xffffffffu, vw, o);
        vb += __shfl_down_sync(0xffffffffu, vb, o);
    }
    if ((t & 31) == 0) { sw[t >> 5] = vw; sb[t >> 5] = vb; }
    __syncthreads();
    if (t < 32) {
        vw = sw[t]; vb = sb[t];
        #pragma unroll
        for (int o = 16; o > 0; o >>= 1) {
            vw += __shfl_down_sync(0xffffffffu, vw, o);
            vb += __shfl_down_sync(0xffffffffu, vb, o);
        }
        if (t == 0) { g_mw = vw / (float)Hc; g_mb = vb / (float)Hc; }
    }
}

__device__ __forceinline__ void bsplit_store4(bf16* __restrict__ ph, bf16* __restrict__ pl,
                                              float v0, float v1, float v2, float v3) {
    bf16 h0 = __float2bfloat16(v0), h1 = __float2bfloat16(v1);
    bf16 h2 = __float2bfloat16(v2), h3 = __float2bfloat16(v3);
    ((__nv_bfloat162*)ph)[0] = __halves2bfloat162(h0, h1);
    ((__nv_bfloat162*)ph)[1] = __halves2bfloat162(h2, h3);
    ((__nv_bfloat162*)pl)[0] = __halves2bfloat162(
        __float2bfloat16(v0 - __bfloat162float(h0)), __float2bfloat16(v1 - __bfloat162float(h1)));
    ((__nv_bfloat162*)pl)[1] = __halves2bfloat162(
        __float2bfloat16(v2 - __bfloat162float(h2)), __float2bfloat16(v3 - __bfloat162float(h3)));
}

__global__ void affine_k(const float4* __restrict__ x, bf16* __restrict__ xh, bf16* __restrict__ xl) {
    long i = (long)blockIdx.x * blockDim.x + threadIdx.x;
    float a = 1.0f + g_mw, c = g_mb;
    float4 v = x[i];
    bsplit_store4(xh + i * 4, xl + i * 4, v.x * a + c, v.y * a + c, v.z * a + c, v.w * a + c);
}

// W [K,N] fp32 -> WT hi/lo [N,K] bf16  (MLP weights)
__global__ void wsplitT(const float* __restrict__ W, bf16* __restrict__ th, bf16* __restrict__ tl,
                        int K, int N) {
    __shared__ float t[32][33];
    int k0 = blockIdx.x * 32, n0 = blockIdx.y * 32;
    int tx = threadIdx.x, ty = threadIdx.y;
    #pragma unroll
    for (int i = ty; i < 32; i += 8)
        t[i][tx] = W[(long)(k0 + i) * N + n0 + tx];
    __syncthreads();
    #pragma unroll
    for (int i = ty; i < 32; i += 8) {
        float v = t[tx][i];
        bf16 h = __float2bfloat16(v);
        long o = (long)(n0 + i) * K + k0 + tx;
        th[o] = h;
        tl[o] = __float2bfloat16(v - __bfloat162float(h));
    }
}

// W [K,N] fp32 -> WT fp16 [N,K]  (attention weights)
__global__ void wsplit1(const float* __restrict__ W, f16* __restrict__ th, int K, int N) {
    __shared__ float t[32][33];
    int k0 = blockIdx.x * 32, n0 = blockIdx.y * 32;
    int tx = threadIdx.x, ty = threadIdx.y;
    #pragma unroll
    for (int i = ty; i < 32; i += 8)
        t[i][tx] = W[(long)(k0 + i) * N + n0 + tx];
    __syncthreads();
    #pragma unroll
    for (int i = ty; i < 32; i += 8)
        th[(long)(n0 + i) * K + k0 + tx] = __float2half(t[tx][i]);
}

__global__ void bcat(const float* __restrict__ bq, const float* __restrict__ bk,
                     const float* __restrict__ bv, float* __restrict__ o) {
    int i = blockIdx.x * 256 + threadIdx.x;
    o[i] = i < Hc ? bq[i] : (i < 2 * Hc ? bk[i - Hc] : bv[i - 2 * Hc]);
}

// v slice of qkv (fp16, ld=3072, offset 2048) -> vT fp16 [(B*NH), HD, M]
__global__ void vsplitT(const f16* __restrict__ v, f16* __restrict__ th) {
    __shared__ float t[32][33];
    int z = blockIdx.z, zb = z >> 3, zh = z & 7;
    int m0 = blockIdx.x * 32, d0 = blockIdx.y * 32;
    int tx = threadIdx.x, ty = threadIdx.y;
    #pragma unroll
    for (int i = ty; i < 32; i += 8)
        t[i][tx] = __half2float(v[((long)zb * Mc + m0 + i) * 3072 + 2048 + zh * HDc + d0 + tx]);
    __syncthreads();
    #pragma unroll
    for (int i = ty; i < 32; i += 8)
        th[((long)z * HDc + d0 + i) * Mc + m0 + tx] = __float2half(t[tx][i]);
}

__global__ void ln_k(const float* __restrict__ in, const float* __restrict__ g,
                     const float* __restrict__ be, f16* __restrict__ oh) {
    long row = blockIdx.x;
    const float4* p = (const float4*)(in + row * Hc);
    int t = threadIdx.x;
    float4 v = p[t];
    float s  = v.x + v.y + v.z + v.w;
    float s2 = v.x * v.x + v.y * v.y + v.z * v.z + v.w * v.w;
    __shared__ float ss[8], ss2[8];
    #pragma unroll
    for (int of = 16; of > 0; of >>= 1) {
        s  += __shfl_down_sync(0xffffffffu, s, of);
        s2 += __shfl_down_sync(0xffffffffu, s2, of);
    }
    if ((t & 31) == 0) { ss[t >> 5] = s; ss2[t >> 5] = s2; }
    __syncthreads();
    __shared__ float mu_s, ri_s;
    if (t == 0) {
        float a = 0.f, b2 = 0.f;
        #pragma unroll
        for (int i = 0; i < 8; i++) { a += ss[i]; b2 += ss2[i]; }
        float mu = a / (float)Hc;
        mu_s = mu;
        ri_s = rsqrtf(b2 / (float)Hc - mu * mu + EPSc);
    }
    __syncthreads();
    float mu = mu_s, ri = ri_s;
    float4 gv = ((const float4*)g)[t];
    float4 bv = ((const float4*)be)[t];
    long o = row * Hc + t * 4;
    ((__half2*)(oh + o))[0] = __halves2half2(
        __float2half((v.x - mu) * ri * gv.x + bv.x), __float2half((v.y - mu) * ri * gv.y + bv.y));
    ((__half2*)(oh + o))[1] = __halves2half2(
        __float2half((v.z - mu) * ri * gv.z + bv.z), __float2half((v.w - mu) * ri * gv.w + bv.w));
}

// ---------------------------------------------------------------------------
// mma.sync GEMM (unchanged engine from R5)
// ---------------------------------------------------------------------------
#define NST 3
#define TILEB 16384                 // one 128x64 16-bit tile

template<typename T>
__device__ __forceinline__ void tile_cp(uint32_t sm, const T* __restrict__ g, long ld, int tid) {
    int r = tid >> 3;
    int c16 = tid & 7;
    const char* gp = (const char*)(g + c16 * 8);
    #pragma unroll
    for (int i = 0; i < 4; i++) {
        int row = r + i * 32;
        uint32_t so = sm + row * 128 + ((c16 ^ (row & 7)) << 4);
        cp_async16(so, gp + (long)row * ld * 2);
    }
}

template<typename T, int OUT, int EPI>
__device__ __forceinline__ void store_pair(long off, long c, float v0, float v1,
                                           const float* __restrict__ bias,
                                           const float* __restrict__ Res,
                                           float* __restrict__ C,
                                           T* __restrict__ Ch, T* __restrict__ Cl,
                                           float alpha) {
    v0 *= alpha; v1 *= alpha;
    if (EPI & 1) { v0 += bias[c]; v1 += bias[c + 1]; }
    if (EPI & 2) { v0 = fmaxf(v0, 0.f); v1 = fmaxf(v1, 0.f); }
    if (EPI & 4) {
        float2 rv = *(const float2*)(Res + off);
        v0 += rv.x; v1 += rv.y;
    }
    if (OUT == 0) {
        *(float2*)(C + off) = make_float2(v0, v1);
    } else {
        T h0 = TT<T>::c(v0), h1 = TT<T>::c(v1);
        *(typename TT<T>::T2*)(Ch + off) = TT<T>::pack(h0, h1);
        if (OUT == 2) {
            *(typename TT<T>::T2*)(Cl + off) = TT<T>::pack(
                TT<T>::c(v0 - TT<T>::f(h0)), TT<T>::c(v1 - TT<T>::f(h1)));
        }
    }
}

template<typename T, bool SPLIT, int OUT, int EPI>
__global__ void __launch_bounds__(256, SPLIT ? 1 : 2)
mmk(const T* __restrict__ Ah, const T* __restrict__ Al,
    const T* __restrict__ Bh, const T* __restrict__ Bl,
    const float* __restrict__ bias, const float* __restrict__ Res,
    float* __restrict__ C, T* __restrict__ Ch, T* __restrict__ Cl,
    int Kdim, int lda, int ldb, int ldc,
    int nh, long sA0, long sA1, long sB0, long sB1, long sC0, long sC1,
    float alpha)
{
    extern __shared__ __align__(1024) char smem[];
    constexpr int NTILE = SPLIT ? 4 : 2;
    constexpr int STAGEB = NTILE * TILEB;
    constexpr int BOFF = SPLIT ? 2 * TILEB : TILEB;

    const uint32_t sb = smem_u32(smem);
    const int tid = threadIdx.x;
    const int wid = tid >> 5, l = tid & 31;
    const int wm = wid >> 2, wn = wid & 3;

    const int z = blockIdx.z;
    const long zb = z / nh, zh = z - zb * (long)nh;
    const long row0 = (long)blockIdx.y * 128;
    const long col0 = (long)blockIdx.x * 128;

    const long aoff = zb * sA0 + zh * sA1 + row0 * lda;
    const long boff = zb * sB0 + zh * sB1 + col0 * ldb;
    const T* pAh = Ah + aoff;
    const T* pAl = SPLIT ? (Al + aoff) : nullptr;
    const T* pBh = Bh + boff;
    const T* pBl = SPLIT ? (Bl + boff) : nullptr;

    float acc[4][4][4];
    #pragma unroll
    for (int i = 0; i < 4; i++)
        #pragma unroll
        for (int j = 0; j < 4; j++)
            #pragma unroll
            for (int r = 0; r < 4; r++) acc[i][j][r] = 0.0f;

    const int nchunk = Kdim >> 6;

    #pragma unroll
    for (int s = 0; s < NST - 1; s++) {
        if (s < nchunk) {
            uint32_t st = sb + s * STAGEB;
            long k0 = (long)s << 6;
            tile_cp(st,        pAh + k0, lda, tid);
            if (SPLIT) tile_cp(st + TILEB, pAl + k0, lda, tid);
            tile_cp(st + BOFF, pBh + k0, ldb, tid);
            if (SPLIT) tile_cp(st + BOFF + TILEB, pBl + k0, ldb, tid);
        }
        cp_commit();
    }

    const int ar = l & 15, asel = l >> 4, swa = l & 7;
    const int br = ((l >> 4) << 3) + (l & 7), bsel = (l >> 3) & 1;
    const int swb = br & 7;

    for (int c = 0; c < nchunk; c++) {
        cp_wait<1>();
        __syncthreads();
        if (c + 2 < nchunk) {
            uint32_t st = sb + ((c + 2) % NST) * STAGEB;
            long k0 = (long)(c + 2) << 6;
            tile_cp(st,        pAh + k0, lda, tid);
            if (SPLIT) tile_cp(st + TILEB, pAl + k0, lda, tid);
            tile_cp(st + BOFF, pBh + k0, ldb, tid);
            if (SPLIT) tile_cp(st + BOFF + TILEB, pBl + k0, ldb, tid);
        }
        cp_commit();

        const uint32_t st = sb + (c % NST) * STAGEB;
        #pragma unroll
        for (int kp = 0; kp < 4; kp++) {
            uint32_t aH[4][4], aL[4][4], bH[4][2], bL[4][2];
            #pragma unroll
            for (int mt = 0; mt < 4; mt++) {
                int row = wm * 64 + mt * 16 + ar;
                uint32_t col = ((kp * 2 + asel) ^ swa) << 4;
                uint32_t ad = st + row * 128 + col;
                ldsm4(aH[mt][0], aH[mt][1], aH[mt][2], aH[mt][3], ad);
                if (SPLIT) ldsm4(aL[mt][0], aL[mt][1], aL[mt][2], aL[mt][3], ad + TILEB);
            }
            #pragma unroll
            for (int np = 0; np < 2; np++) {
                int row = wn * 32 + np * 16 + br;
                uint32_t col = ((kp * 2 + bsel) ^ swb) << 4;
                uint32_t bd = st + BOFF + row * 128 + col;
                ldsm4(bH[np*2][0], bH[np*2][1], bH[np*2+1][0], bH[np*2+1][1], bd);
                if (SPLIT) ldsm4(bL[np*2][0], bL[np*2][1], bL[np*2+1][0], bL[np*2+1][1], bd + TILEB);
            }
            #pragma unroll
            for (int mt = 0; mt < 4; mt++)
                #pragma unroll
                for (int nt = 0; nt < 4; nt++) {
                    mma16816<T>(acc[mt][nt], aH[mt], bH[nt][0], bH[nt][1]);
                    if (SPLIT) {
                        mma16816<T>(acc[mt][nt], aH[mt], bL[nt][0], bL[nt][1]);
                        mma16816<T>(acc[mt][nt], aL[mt], bH[nt][0], bH[nt][1]);
                    }
                }
        }
        __syncthreads();
    }

    const long Rw = row0 + wm * 64;
    const long Cw = col0 + wn * 32;
    const long base = zb * sC0 + zh * sC1;
    const int lr = l >> 2, lc = (l & 3) * 2;
    #pragma unroll
    for (int mt = 0; mt < 4; mt++) {
        long r0 = Rw + mt * 16 + lr;
        #pragma unroll
        for (int nt = 0; nt < 4; nt++) {
            long cc = Cw + nt * 8 + lc;
            store_pair<T, OUT, EPI>(base + r0 * ldc + cc, cc, acc[mt][nt][0], acc[mt][nt][1],
                                    bias, Res, C, Ch, Cl, alpha);
            store_pair<T, OUT, EPI>(base + (r0 + 8) * ldc + cc, cc, acc[mt][nt][2], acc[mt][nt][3],
                                    bias, Res, C, Ch, Cl, alpha);
        }
    }
}

// ---------------------------------------------------------------------------
// Fused attention: per CTA = one 128-row q-tile of one (b,h).
//   8 warps, each owns 16 q-rows x full 128-col key range.
//   S = Q@K^T (fp16 mma, fp32 acc), scale, zero-diag, online softmax,
//   P (fp16, from register relayout) @ V' accumulated into O (fp32).
//   K/V' tiles double-buffered via cp.async. Q in smem (2 subtiles).
// smem: Q[2] | buf0: K[2] V[2] | buf1: K[2] V[2]  = 10 * TILEB = 160 KB
// ---------------------------------------------------------------------------
__global__ void __launch_bounds__(256, 1)
fattn(const f16* __restrict__ qkv, const f16* __restrict__ vt, f16* __restrict__ outp)
{
    extern __shared__ __align__(1024) char smem[];
    const uint32_t sb = smem_u32(smem);
    const int tid = threadIdx.x;
    const int w = tid >> 5, l = tid & 31;
    const int by = blockIdx.x;                 // q-tile 0..3
    const int z  = blockIdx.y;                 // b*8 + h
    const int b = z >> 3, h = z & 7;

    const long qrow0 = (long)b * Mc + by * 128;
    const f16* pQ  = qkv + qrow0 * 3072 + h * HDc;
    const f16* pK0 = qkv + (long)b * Mc * 3072 + Hc + h * HDc;
    const f16* pV0 = vt + (long)z * HDc * Mc;

    // prologue: Q (2 subtiles) + K0/V0 into buffer 0
    tile_cp(sb + 0 * TILEB, pQ,      3072, tid);
    tile_cp(sb + 1 * TILEB, pQ + 64, 3072, tid);
    tile_cp(sb + 2 * TILEB, pK0,      3072, tid);
    tile_cp(sb + 3 * TILEB, pK0 + 64, 3072, tid);
    tile_cp(sb + 4 * TILEB, pV0,      Mc, tid);
    tile_cp(sb + 5 * TILEB, pV0 + 64, Mc, tid);
    cp_commit();

    float oacc[16][4];
    #pragma unroll
    for (int i = 0; i < 16; i++)
        #pragma unroll
        for (int c = 0; c < 4; c++) oacc[i][c] = 0.0f;
    float mprev[2] = {-1e30f, -1e30f};
    float lsum[2]  = {0.0f, 0.0f};

    const int ar = l & 15, asel = l >> 4;
    const int br = ((l >> 4) << 3) + (l & 7), bsel = (l >> 3) & 1;
    const int sw = l & 7;
    const float alpha = 0.08838834764831845f;   // 1/sqrt(128)

    for (int j = 0; j < 4; j++) {
        const int buf = j & 1;
        if (j < 3) {
            const int nb_ = buf ^ 1;
            const f16* pK = pK0 + (long)(j + 1) * 128 * 3072;
            const f16* pV = pV0 + (j + 1) * 128;
            tile_cp(sb + (2 + nb_ * 4 + 0) * TILEB, pK,      3072, tid);
            tile_cp(sb + (2 + nb_ * 4 + 1) * TILEB, pK + 64, 3072, tid);
            tile_cp(sb + (2 + nb_ * 4 + 2) * TILEB, pV,      Mc, tid);
            tile_cp(sb + (2 + nb_ * 4 + 3) * TILEB, pV + 64, Mc, tid);
            cp_commit();
            cp_wait<1>();
        } else {
            cp_wait<0>();
        }
        __syncthreads();

        const uint32_t sK = sb + (2 + buf * 4) * TILEB;
        const uint32_t sV = sK + 2 * TILEB;

        // ---- S = Q @ K^T  (16 q-rows x 128 keys per warp)
        float sacc[16][4];
        #pragma unroll
        for (int i = 0; i < 16; i++)
            #pragma unroll
            for (int c = 0; c < 4; c++) sacc[i][c] = 0.0f;

        #pragma unroll
        for (int kp = 0; kp < 8; kp++) {
            uint32_t aq[4];
            uint32_t qa = sb + (kp >> 2) * TILEB + (w * 16 + ar) * 128
                        + ((((kp & 3) * 2 + asel) ^ sw) << 4);
            ldsm4(aq[0], aq[1], aq[2], aq[3], qa);
            #pragma unroll
            for (int nb = 0; nb < 8; nb++) {
                uint32_t b0, b1, b2, b3;
                uint32_t ka = sK + (kp >> 2) * TILEB + (nb * 16 + br) * 128
                            + ((((kp & 3) * 2 + bsel) ^ sw) << 4);
                ldsm4(b0, b1, b2, b3, ka);
                mma16816<f16>(sacc[nb * 2],     aq, b0, b1);
                mma16816<f16>(sacc[nb * 2 + 1], aq, b2, b3);
            }
        }

        // ---- scale + zero-diagonal (mask applied BEFORE softmax, value 0)
        #pragma unroll
        for (int i = 0; i < 16; i++)
            #pragma unroll
            for (int c = 0; c < 4; c++) sacc[i][c] *= alpha;
        if (by == j) {
            int r0 = w * 16 + (l >> 2);
            #pragma unroll
            for (int nt = 0; nt < 16; nt++) {
                int cb = nt * 8 + (l & 3) * 2;
                if (cb     == r0)     sacc[nt][0] = 0.0f;
                if (cb + 1 == r0)     sacc[nt][1] = 0.0f;
                if (cb     == r0 + 8) sacc[nt][2] = 0.0f;
                if (cb + 1 == r0 + 8) sacc[nt][3] = 0.0f;
            }
        }

        // ---- online softmax (row spread across quad: lanes l^1, l^2)
        #pragma unroll
        for (int g = 0; g < 2; g++) {
            float mx = -1e30f;
            #pragma unroll
            for (int nt = 0; nt < 16; nt++)
                mx = fmaxf(mx, fmaxf(sacc[nt][2 * g], sacc[nt][2 * g + 1]));
            mx = fmaxf(mx, __shfl_xor_sync(0xffffffffu, mx, 1));
            mx = fmaxf(mx, __shfl_xor_sync(0xffffffffu, mx, 2));
            float mnew = fmaxf(mprev[g], mx);
            float sc = __expf(mprev[g] - mnew);
            float sum = 0.0f;
            #pragma unroll
            for (int nt = 0; nt < 16; nt++) {
                float e0 = __expf(sacc[nt][2 * g]     - mnew);
                float e1 = __expf(sacc[nt][2 * g + 1] - mnew);
                sacc[nt][2 * g] = e0; sacc[nt][2 * g + 1] = e1;
                sum += e0 + e1;
            }
            sum += __shfl_xor_sync(0xffffffffu, sum, 1);
            sum += __shfl_xor_sync(0xffffffffu, sum, 2);
            lsum[g] = lsum[g] * sc + sum;
            mprev[g] = mnew;
            #pragma unroll
            for (int nt = 0; nt < 16; nt++) {
                oacc[nt][2 * g]     *= sc;
                oacc[nt][2 * g + 1] *= sc;
            }
        }

        // ---- P: C-layout fp32 -> A-layout fp16 (register identity)
        uint32_t aP[8][4];
        #pragma unroll
        for (int t = 0; t < 8; t++) {
            aP[t][0] = f2h2(sacc[2*t][0],   sacc[2*t][1]);
            aP[t][1] = f2h2(sacc[2*t][2],   sacc[2*t][3]);
            aP[t][2] = f2h2(sacc[2*t+1][0], sacc[2*t+1][1]);
            aP[t][3] = f2h2(sacc[2*t+1][2], sacc[2*t+1][3]);
        }

        // ---- O += P @ V'
        #pragma unroll
        for (int t = 0; t < 8; t++) {
            #pragma unroll
            for (int nb = 0; nb < 8; nb++) {
                uint32_t b0, b1, b2, b3;
                uint32_t va = sV + (t >> 2) * TILEB + (nb * 16 + br) * 128
                            + ((((t & 3) * 2 + bsel) ^ sw) << 4);
                ldsm4(b0, b1, b2, b3, va);
                mma16816<f16>(oacc[nb * 2],     aP[t], b0, b1);
                mma16816<f16>(oacc[nb * 2 + 1], aP[t], b2, b3);
            }
        }
        __syncthreads();
    }

    // ---- normalize + store (heads interleaved into [B*M, H])
    #pragma unroll
    for (int g = 0; g < 2; g++) {
        float inv = 1.0f / lsum[g];
        long m = qrow0 + w * 16 + (l >> 2) + 8 * g;
        f16* op = outp + m * Hc + h * HDc + (l & 3) * 2;
        #pragma unroll
        for (int nt = 0; nt < 16; nt++) {
            float v0 = oacc[nt][2 * g] * inv, v1 = oacc[nt][2 * g + 1] * inv;
            *(__half2*)(op + nt * 8) = __halves2half2(__float2half(v0), __float2half(v1));
        }
    }
}

// ---------------------------------------------------------------------------
// Launch
// ---------------------------------------------------------------------------
extern "C" void kernel_launch(void* const* d_in, const int* in_sizes, int n_in,
                              void* d_out, int out_size)
{
    const float* x      = (const float*)d_in[0];
    const float* conv_w = (const float*)d_in[1];
    const float* conv_b = (const float*)d_in[2];
    const float* w1 = (const float*)d_in[3];
    const float* b1 = (const float*)d_in[4];
    const float* w2 = (const float*)d_in[5];
    const float* b2 = (const float*)d_in[6];
    const float* ln_g = (const float*)d_in[7];
    const float* ln_b = (const float*)d_in[8];
    const float* wq = (const float*)d_in[9];
    const float* bq = (const float*)d_in[10];
    const float* wk = (const float*)d_in[11];
    const float* bk = (const float*)d_in[12];
    const float* wv = (const float*)d_in[13];
    const float* bv = (const float*)d_in[14];
    const float* wo = (const float*)d_in[15];
    const float* bo = (const float*)d_in[16];
    const float* wp = (const float*)d_in[17];
    const float* bp = (const float*)d_in[18];
    float* out = (float*)d_out;

    #define SYM(p, s) void* p; cudaGetSymbolAddress(&p, s)
    SYM(xah, g_xah); SYM(xal, g_xal);
    SYM(h1h, g_h1h); SYM(h1l, g_h1l);
    SYM(xreg, g_xreg);
    SYM(xnh, g_xnh);
    SYM(qkv, g_qkv); SYM(vth, g_vth);
    SYM(ch, g_ch);
    SYM(t1h, g_t1h);
    SYM(w1h, g_w1h); SYM(w1l, g_w1l);
    SYM(w2h, g_w2h); SYM(w2l, g_w2l);
    SYM(wqkv, g_wqkv); SYM(bqkv, g_bqkv);
    SYM(woh, g_woh); SYM(wph, g_wph);
    #undef SYM

    const int SMB_S = NST * 4 * TILEB;   // 196608 (split)
    const int SMB_1 = NST * 2 * TILEB;   //  98304 (single)
    const int SMB_F = 10 * TILEB;        // 163840 (fattn)
    cudaFuncSetAttribute(mmk<bf16,true,2,3>, cudaFuncAttributeMaxDynamicSharedMemorySize, SMB_S);
    cudaFuncSetAttribute(mmk<bf16,true,0,1>, cudaFuncAttributeMaxDynamicSharedMemorySize, SMB_S);
    cudaFuncSetAttribute(mmk<f16,false,1,1>, cudaFuncAttributeMaxDynamicSharedMemorySize, SMB_1);
    cudaFuncSetAttribute(mmk<f16,false,0,5>, cudaFuncAttributeMaxDynamicSharedMemorySize, SMB_1);
    cudaFuncSetAttribute(fattn, cudaFuncAttributeMaxDynamicSharedMemorySize, SMB_F);

    const int BMrows = Bc * Mc;  // 32768

    // 1. conv means, affine + bf16 split
    means_k<<<1, 1024>>>(conv_w, conv_b);
    affine_k<<<(unsigned)(BMM / 4 / 256), 256>>>((const float4*)x, (bf16*)xah, (bf16*)xal);

    // 2. weight transposes: bf16 split for MLP; fp16 concat for q|k|v; wo, wp
    wsplitT<<<dim3(Mc/32, Hc/32), dim3(32,8)>>>(w1, (bf16*)w1h, (bf16*)w1l, Mc, Hc);
    wsplitT<<<dim3(Hc/32, Hc/32), dim3(32,8)>>>(w2, (bf16*)w2h, (bf16*)w2l, Hc, Hc);
    wsplit1<<<dim3(Hc/32, Hc/32), dim3(32,8)>>>(wq, (f16*)wqkv,                    Hc, Hc);
    wsplit1<<<dim3(Hc/32, Hc/32), dim3(32,8)>>>(wk, (f16*)wqkv + (size_t)Hc*Hc,    Hc, Hc);
    wsplit1<<<dim3(Hc/32, Hc/32), dim3(32,8)>>>(wv, (f16*)wqkv + (size_t)2*Hc*Hc,  Hc, Hc);
    wsplit1<<<dim3(Hc/32, Hc/32), dim3(32,8)>>>(wo, (f16*)woh, Hc, Hc);
    wsplit1<<<dim3(Hc/32, Hc/32), dim3(32,8)>>>(wp, (f16*)wph, Hc, Hc);
    bcat<<<12, 256>>>(bq, bk, bv, (float*)bqkv);

    // 3. h1 = relu(xa @ w1 + b1) -> bf16 split (3-term)
    mmk<bf16,true,2,3><<<dim3(Hc/128, BMrows/128, 1), 256, SMB_S>>>(
        (bf16*)xah, (bf16*)xal, (bf16*)w1h, (bf16*)w1l, b1, nullptr,
        nullptr, (bf16*)h1h, (bf16*)h1l,
        Mc, Mc, Mc, Hc, 1, 0,0,0,0,0,0, 1.0f);

    // 4. xreg = h1 @ w2 + b2 (fp32)  (3-term)
    mmk<bf16,true,0,1><<<dim3(Hc/128, BMrows/128, 1), 256, SMB_S>>>(
        (bf16*)h1h, (bf16*)h1l, (bf16*)w2h, (bf16*)w2l, b2, nullptr,
        (float*)xreg, nullptr, nullptr,
        Hc, Hc, Hc, Hc, 1, 0,0,0,0,0,0, 1.0f);

    // 5. layernorm -> fp16
    ln_k<<<BMrows, 256>>>((const float*)xreg, ln_g, ln_b, (f16*)xnh);

    // 6. fused q|k|v projection: [32768,1024] @ [1024,3072] -> fp16 [32768,3072]
    mmk<f16,false,1,1><<<dim3(3*Hc/128, BMrows/128, 1), 256, SMB_1>>>(
        (f16*)xnh, nullptr, (f16*)wqkv, nullptr, (const float*)bqkv, nullptr,
        nullptr, (f16*)qkv, nullptr, Hc, Hc, Hc, 3*Hc, 1, 0,0,0,0,0,0, 1.0f);

    // 7. vT fp16 [B*NH, HD, M] from qkv's v slice
    vsplitT<<<dim3(Mc/32, HDc/32, Bc*NHc), dim3(32,8)>>>((const f16*)qkv, (f16*)vth);

    // 8. fused attention (scores + zero-diag softmax + ctx) -> g_ch
    fattn<<<dim3(Mc/128, Bc*NHc), 256, SMB_F>>>((const f16*)qkv, (const f16*)vth, (f16*)ch);

    // 9. t1 = ctx @ wo + bo -> fp16
    mmk<f16,false,1,1><<<dim3(Hc/128, BMrows/128, 1), 256, SMB_1>>>(
        (f16*)ch, nullptr, (f16*)woh, nullptr, bo, nullptr,
        nullptr, (f16*)t1h, nullptr, Hc, Hc, Hc, Hc, 1, 0,0,0,0,0,0, 1.0f);

    // 10. out = t1 @ wp + bp + xreg (fp32)
    mmk<f16,false,0,5><<<dim3(Hc/128, BMrows/128, 1), 256, SMB_1>>>(
        (f16*)t1h, nullptr, (f16*)wph, nullptr, bp, (const float*)xreg,
        out, nullptr, nullptr, Hc, Hc, Hc, Hc, 1, 0,0,0,0,0,0, 1.0f);
}

// round 9
// speedup vs baseline: 8.6142x; 1.4213x over previous
#include <cuda_runtime.h>
#include <cuda_fp16.h>
#include <cstdint>

#define Bc  64
#define Mc  512
#define Hc  1024
#define NHc 8
#define HDc 128
#define EPSc 1e-5f

typedef __half f16;

#define BMH ((size_t)Bc*Mc*Hc)
#define BMM ((size_t)Bc*Mc*Mc)

// ---------------------------------------------------------------------------
// Scratch (static device globals — allocation-free)
// ---------------------------------------------------------------------------
__device__ float g_mw, g_mb;
__device__ f16 g_xah[BMM];
__device__ f16 g_h1[BMH];
__device__ float g_xreg[BMH];
__device__ f16 g_xnh[BMH];
__device__ f16 g_qkv[(size_t)Bc*Mc*3*Hc];         // [B*M, 3072] = q|k|v
__device__ f16 g_vth[BMH];                        // [B*NH, 128, 512]
__device__ f16 g_ch[BMH];
// fp16 weights
__device__ f16 g_w1t[(size_t)Hc*Mc];              // [N,K]
__device__ f16 g_w2t[(size_t)Hc*Hc];              // [N,K]
__device__ f16 g_wqkv[(size_t)3*Hc*Hc];           // [3072, 1024]
__device__ f16 g_wo16[(size_t)Hc*Hc];             // wo row-major (untransposed!)
__device__ f16 g_wpt[(size_t)Hc*Hc];              // [N,K]
__device__ f16 g_wopT[(size_t)Hc*Hc];             // (wo@wp)^T in [N,K]
__device__ float g_bqkv[3*Hc];
__device__ float g_bop[Hc];                       // bo@wp + bp

// ---------------------------------------------------------------------------
// PTX helpers (baseline PTX only — no tcgen05 on compute_103)
// ---------------------------------------------------------------------------
__device__ __forceinline__ uint32_t smem_u32(const void* p) {
    uint32_t a;
    asm("{ .reg .u64 t; cvta.to.shared.u64 t, %1; cvt.u32.u64 %0, t; }"
        : "=r"(a) : "l"(p));
    return a;
}

// pack two fp32 -> u32 {hi:f16(hi), lo:f16(lo)}
__device__ __forceinline__ uint32_t f2h2(float lo, float hi) {
    uint32_t r;
    asm("cvt.rn.f16x2.f32 %0, %1, %2;" : "=r"(r) : "f"(hi), "f"(lo));
    return r;
}

__device__ __forceinline__ void cp_async16(uint32_t saddr, const void* gaddr) {
    asm volatile("cp.async.cg.shared.global [%0], [%1], 16;\n"
                 :: "r"(saddr), "l"(gaddr));
}
__device__ __forceinline__ void cp_commit() {
    asm volatile("cp.async.commit_group;\n" ::: "memory");
}
template<int N>
__device__ __forceinline__ void cp_wait() {
    asm volatile("cp.async.wait_group %0;\n" :: "n"(N) : "memory");
}

__device__ __forceinline__ void ldsm4(uint32_t& r0, uint32_t& r1, uint32_t& r2, uint32_t& r3,
                                      uint32_t addr) {
    asm volatile("ldmatrix.sync.aligned.m8n8.x4.shared.b16 {%0,%1,%2,%3}, [%4];"
                 : "=r"(r0), "=r"(r1), "=r"(r2), "=r"(r3) : "r"(addr));
}

__device__ __forceinline__ void mma16816(float* c, const uint32_t* a, uint32_t b0, uint32_t b1) {
    asm volatile("mma.sync.aligned.m16n8k16.row.col.f32.f16.f16.f32 "
                 "{%0,%1,%2,%3}, {%4,%5,%6,%7}, {%8,%9}, {%0,%1,%2,%3};"
                 : "+f"(c[0]), "+f"(c[1]), "+f"(c[2]), "+f"(c[3])
                 : "r"(a[0]), "r"(a[1]), "r"(a[2]), "r"(a[3]), "r"(b0), "r"(b1));
}

// ---------------------------------------------------------------------------
// small kernels
// ---------------------------------------------------------------------------
__global__ void means_k(const float* __restrict__ w, const float* __restrict__ b) {
    __shared__ float sw[32], sb[32];
    int t = threadIdx.x;
    float vw = w[t], vb = b[t];
    #pragma unroll
    for (int o = 16; o > 0; o >>= 1) {
        vw += __shfl_down_sync(0xffffffffu, vw, o);
        vb += __shfl_down_sync(0xffffffffu, vb, o);
    }
    if ((t & 31) == 0) { sw[t >> 5] = vw; sb[t >> 5] = vb; }
    __syncthreads();
    if (t < 32) {
        vw = sw[t]; vb = sb[t];
        #pragma unroll
        for (int o = 16; o > 0; o >>= 1) {
            vw += __shfl_down_sync(0xffffffffu, vw, o);
            vb += __shfl_down_sync(0xffffffffu, vb, o);
        }
        if (t == 0) { g_mw = vw / (float)Hc; g_mb = vb / (float)Hc; }
    }
}

__global__ void affine_k(const float4* __restrict__ x, f16* __restrict__ xh) {
    long i = (long)blockIdx.x * blockDim.x + threadIdx.x;
    float a = 1.0f + g_mw, c = g_mb;
    float4 v = x[i];
    ((__half2*)(xh + i * 4))[0] = __halves2half2(__float2half(v.x * a + c), __float2half(v.y * a + c));
    ((__half2*)(xh + i * 4))[1] = __halves2half2(__float2half(v.z * a + c), __float2half(v.w * a + c));
}

// W [K,N] fp32 -> WT fp16 [N,K]
__global__ void wsplit1(const float* __restrict__ W, f16* __restrict__ th, int K, int N) {
    __shared__ float t[32][33];
    int k0 = blockIdx.x * 32, n0 = blockIdx.y * 32;
    int tx = threadIdx.x, ty = threadIdx.y;
    #pragma unroll
    for (int i = ty; i < 32; i += 8)
        t[i][tx] = W[(long)(k0 + i) * N + n0 + tx];
    __syncthreads();
    #pragma unroll
    for (int i = ty; i < 32; i += 8)
        th[(long)(n0 + i) * K + k0 + tx] = __float2half(t[tx][i]);
}

// plain fp32 -> fp16 cast (no transpose), 4 elems/thread
__global__ void wcast(const float4* __restrict__ W, f16* __restrict__ o) {
    long i = (long)blockIdx.x * blockDim.x + threadIdx.x;
    float4 v = W[i];
    ((__half2*)(o + i * 4))[0] = __halves2half2(__float2half(v.x), __float2half(v.y));
    ((__half2*)(o + i * 4))[1] = __halves2half2(__float2half(v.z), __float2half(v.w));
}

__global__ void bcat(const float* __restrict__ bq, const float* __restrict__ bk,
                     const float* __restrict__ bv, float* __restrict__ o) {
    int i = blockIdx.x * 256 + threadIdx.x;
    o[i] = i < Hc ? bq[i] : (i < 2 * Hc ? bk[i - Hc] : bv[i - 2 * Hc]);
}

// bop[n] = bp[n] + sum_j bo[j] * wp[j,n]
__global__ void bop_k(const float* __restrict__ bo, const float* __restrict__ wp,
                      const float* __restrict__ bp, float* __restrict__ o) {
    int n = blockIdx.x * 256 + threadIdx.x;
    float s = bp[n];
    for (int j = 0; j < Hc; j++) s += bo[j] * wp[(long)j * Hc + n];
    o[n] = s;
}

// v slice of qkv (fp16, ld=3072, offset 2048) -> vT fp16 [(B*NH), HD, M]
__global__ void vsplitT(const f16* __restrict__ v, f16* __restrict__ th) {
    __shared__ float t[32][33];
    int z = blockIdx.z, zb = z >> 3, zh = z & 7;
    int m0 = blockIdx.x * 32, d0 = blockIdx.y * 32;
    int tx = threadIdx.x, ty = threadIdx.y;
    #pragma unroll
    for (int i = ty; i < 32; i += 8)
        t[i][tx] = __half2float(v[((long)zb * Mc + m0 + i) * 3072 + 2048 + zh * HDc + d0 + tx]);
    __syncthreads();
    #pragma unroll
    for (int i = ty; i < 32; i += 8)
        th[((long)z * HDc + d0 + i) * Mc + m0 + tx] = __float2half(t[tx][i]);
}

__global__ void ln_k(const float* __restrict__ in, const float* __restrict__ g,
                     const float* __restrict__ be, f16* __restrict__ oh) {
    long row = blockIdx.x;
    const float4* p = (const float4*)(in + row * Hc);
    int t = threadIdx.x;
    float4 v = p[t];
    float s  = v.x + v.y + v.z + v.w;
    float s2 = v.x * v.x + v.y * v.y + v.z * v.z + v.w * v.w;
    __shared__ float ss[8], ss2[8];
    #pragma unroll
    for (int of = 16; of > 0; of >>= 1) {
        s  += __shfl_down_sync(0xffffffffu, s, of);
        s2 += __shfl_down_sync(0xffffffffu, s2, of);
    }
    if ((t & 31) == 0) { ss[t >> 5] = s; ss2[t >> 5] = s2; }
    __syncthreads();
    __shared__ float mu_s, ri_s;
    if (t == 0) {
        float a = 0.f, b2 = 0.f;
        #pragma unroll
        for (int i = 0; i < 8; i++) { a += ss[i]; b2 += ss2[i]; }
        float mu = a / (float)Hc;
        mu_s = mu;
        ri_s = rsqrtf(b2 / (float)Hc - mu * mu + EPSc);
    }
    __syncthreads();
    float mu = mu_s, ri = ri_s;
    float4 gv = ((const float4*)g)[t];
    float4 bv = ((const float4*)be)[t];
    long o = row * Hc + t * 4;
    ((__half2*)(oh + o))[0] = __halves2half2(
        __float2half((v.x - mu) * ri * gv.x + bv.x), __float2half((v.y - mu) * ri * gv.y + bv.y));
    ((__half2*)(oh + o))[1] = __halves2half2(
        __float2half((v.z - mu) * ri * gv.z + bv.z), __float2half((v.w - mu) * ri * gv.w + bv.w));
}

// ---------------------------------------------------------------------------
// mma.sync fp16 GEMM: C[M,N] = alpha*(A @ B^T) (+bias)(relu)(+res)
//   OUT: 0 = fp32 C, 1 = fp16 Ch.  EPI bits: 1=bias, 2=relu, 4=residual
//   BM=BN=128, BK=64, 256 thr = 8 warps (2x4), warp tile 64x32, 3 stages.
// ---------------------------------------------------------------------------
#define NST 3
#define TILEB 16384                 // one 128x64 fp16 tile

__device__ __forceinline__ void tile_cp(uint32_t sm, const f16* __restrict__ g, long ld, int tid) {
    int r = tid >> 3;
    int c16 = tid & 7;
    const char* gp = (const char*)(g + c16 * 8);
    #pragma unroll
    for (int i = 0; i < 4; i++) {
        int row = r + i * 32;
        uint32_t so = sm + row * 128 + ((c16 ^ (row & 7)) << 4);
        cp_async16(so, gp + (long)row * ld * 2);
    }
}

template<int OUT, int EPI>
__device__ __forceinline__ void store_pair(long off, long c, float v0, float v1,
                                           const float* __restrict__ bias,
                                           const float* __restrict__ Res,
                                           float* __restrict__ C, f16* __restrict__ Ch,
                                           float alpha) {
    v0 *= alpha; v1 *= alpha;
    if (EPI & 1) { v0 += bias[c]; v1 += bias[c + 1]; }
    if (EPI & 2) { v0 = fmaxf(v0, 0.f); v1 = fmaxf(v1, 0.f); }
    if (EPI & 4) {
        float2 rv = *(const float2*)(Res + off);
        v0 += rv.x; v1 += rv.y;
    }
    if (OUT == 0) {
        *(float2*)(C + off) = make_float2(v0, v1);
    } else {
        *(__half2*)(Ch + off) = __halves2half2(__float2half(v0), __float2half(v1));
    }
}

template<int OUT, int EPI>
__global__ void __launch_bounds__(256, 2)
mmk(const f16* __restrict__ Ah, const f16* __restrict__ Bh,
    const float* __restrict__ bias, const float* __restrict__ Res,
    float* __restrict__ C, f16* __restrict__ Ch,
    int Kdim, int lda, int ldb, int ldc,
    int nh, long sA0, long sA1, long sB0, long sB1, long sC0, long sC1,
    float alpha)
{
    extern __shared__ __align__(1024) char smem[];
    constexpr int STAGEB = 2 * TILEB;

    const uint32_t sb = smem_u32(smem);
    const int tid = threadIdx.x;
    const int wid = tid >> 5, l = tid & 31;
    const int wm = wid >> 2, wn = wid & 3;

    const int z = blockIdx.z;
    const long zb = z / nh, zh = z - zb * (long)nh;
    const long row0 = (long)blockIdx.y * 128;
    const long col0 = (long)blockIdx.x * 128;

    const f16* pAh = Ah + zb * sA0 + zh * sA1 + row0 * lda;
    const f16* pBh = Bh + zb * sB0 + zh * sB1 + col0 * ldb;

    float acc[4][4][4];
    #pragma unroll
    for (int i = 0; i < 4; i++)
        #pragma unroll
        for (int j = 0; j < 4; j++)
            #pragma unroll
            for (int r = 0; r < 4; r++) acc[i][j][r] = 0.0f;

    const int nchunk = Kdim >> 6;

    #pragma unroll
    for (int s = 0; s < NST - 1; s++) {
        if (s < nchunk) {
            uint32_t st = sb + s * STAGEB;
            long k0 = (long)s << 6;
            tile_cp(st,         pAh + k0, lda, tid);
            tile_cp(st + TILEB, pBh + k0, ldb, tid);
        }
        cp_commit();
    }

    const int ar = l & 15, asel = l >> 4, swa = l & 7;
    const int br = ((l >> 4) << 3) + (l & 7), bsel = (l >> 3) & 1;
    const int swb = br & 7;

    for (int c = 0; c < nchunk; c++) {
        cp_wait<1>();
        __syncthreads();
        if (c + 2 < nchunk) {
            uint32_t st = sb + ((c + 2) % NST) * STAGEB;
            long k0 = (long)(c + 2) << 6;
            tile_cp(st,         pAh + k0, lda, tid);
            tile_cp(st + TILEB, pBh + k0, ldb, tid);
        }
        cp_commit();

        const uint32_t st = sb + (c % NST) * STAGEB;
        #pragma unroll
        for (int kp = 0; kp < 4; kp++) {
            uint32_t aH[4][4], bH[4][2];
            #pragma unroll
            for (int mt = 0; mt < 4; mt++) {
                int row = wm * 64 + mt * 16 + ar;
                uint32_t ad = st + row * 128 + (((kp * 2 + asel) ^ swa) << 4);
                ldsm4(aH[mt][0], aH[mt][1], aH[mt][2], aH[mt][3], ad);
            }
            #pragma unroll
            for (int np = 0; np < 2; np++) {
                int row = wn * 32 + np * 16 + br;
                uint32_t bd = st + TILEB + row * 128 + (((kp * 2 + bsel) ^ swb) << 4);
                ldsm4(bH[np*2][0], bH[np*2][1], bH[np*2+1][0], bH[np*2+1][1], bd);
            }
            #pragma unroll
            for (int mt = 0; mt < 4; mt++)
                #pragma unroll
                for (int nt = 0; nt < 4; nt++)
                    mma16816(acc[mt][nt], aH[mt], bH[nt][0], bH[nt][1]);
        }
        __syncthreads();
    }

    const long Rw = row0 + wm * 64;
    const long Cw = col0 + wn * 32;
    const long base = zb * sC0 + zh * sC1;
    const int lr = l >> 2, lc = (l & 3) * 2;
    #pragma unroll
    for (int mt = 0; mt < 4; mt++) {
        long r0 = Rw + mt * 16 + lr;
        #pragma unroll
        for (int nt = 0; nt < 4; nt++) {
            long cc = Cw + nt * 8 + lc;
            store_pair<OUT, EPI>(base + r0 * ldc + cc, cc, acc[mt][nt][0], acc[mt][nt][1],
                                 bias, Res, C, Ch, alpha);
            store_pair<OUT, EPI>(base + (r0 + 8) * ldc + cc, cc, acc[mt][nt][2], acc[mt][nt][3],
                                 bias, Res, C, Ch, alpha);
        }
    }
}

// ---------------------------------------------------------------------------
// Fused attention (unchanged from R7): per CTA = one 128-row q-tile of one (b,h).
// smem: Q[2] | buf0: K[2] V[2] | buf1: K[2] V[2]  = 10 * TILEB = 160 KB
// ---------------------------------------------------------------------------
__global__ void __launch_bounds__(256, 1)
fattn(const f16* __restrict__ qkv, const f16* __restrict__ vt, f16* __restrict__ outp)
{
    extern __shared__ __align__(1024) char smem[];
    const uint32_t sb = smem_u32(smem);
    const int tid = threadIdx.x;
    const int w = tid >> 5, l = tid & 31;
    const int by = blockIdx.x;                 // q-tile 0..3
    const int z  = blockIdx.y;                 // b*8 + h
    const int b = z >> 3, h = z & 7;

    const long qrow0 = (long)b * Mc + by * 128;
    const f16* pQ  = qkv + qrow0 * 3072 + h * HDc;
    const f16* pK0 = qkv + (long)b * Mc * 3072 + Hc + h * HDc;
    const f16* pV0 = vt + (long)z * HDc * Mc;

    tile_cp(sb + 0 * TILEB, pQ,      3072, tid);
    tile_cp(sb + 1 * TILEB, pQ + 64, 3072, tid);
    tile_cp(sb + 2 * TILEB, pK0,      3072, tid);
    tile_cp(sb + 3 * TILEB, pK0 + 64, 3072, tid);
    tile_cp(sb + 4 * TILEB, pV0,      Mc, tid);
    tile_cp(sb + 5 * TILEB, pV0 + 64, Mc, tid);
    cp_commit();

    float oacc[16][4];
    #pragma unroll
    for (int i = 0; i < 16; i++)
        #pragma unroll
        for (int c = 0; c < 4; c++) oacc[i][c] = 0.0f;
    float mprev[2] = {-1e30f, -1e30f};
    float lsum[2]  = {0.0f, 0.0f};

    const int ar = l & 15, asel = l >> 4;
    const int br = ((l >> 4) << 3) + (l & 7), bsel = (l >> 3) & 1;
    const int sw = l & 7;
    const float alpha = 0.08838834764831845f;   // 1/sqrt(128)

    for (int j = 0; j < 4; j++) {
        const int buf = j & 1;
        if (j < 3) {
            const int nb_ = buf ^ 1;
            const f16* pK = pK0 + (long)(j + 1) * 128 * 3072;
            const f16* pV = pV0 + (j + 1) * 128;
            tile_cp(sb + (2 + nb_ * 4 + 0) * TILEB, pK,      3072, tid);
            tile_cp(sb + (2 + nb_ * 4 + 1) * TILEB, pK + 64, 3072, tid);
            tile_cp(sb + (2 + nb_ * 4 + 2) * TILEB, pV,      Mc, tid);
            tile_cp(sb + (2 + nb_ * 4 + 3) * TILEB, pV + 64, Mc, tid);
            cp_commit();
            cp_wait<1>();
        } else {
            cp_wait<0>();
        }
        __syncthreads();

        const uint32_t sK = sb + (2 + buf * 4) * TILEB;
        const uint32_t sV = sK + 2 * TILEB;

        float sacc[16][4];
        #pragma unroll
        for (int i = 0; i < 16; i++)
            #pragma unroll
            for (int c = 0; c < 4; c++) sacc[i][c] = 0.0f;

        #pragma unroll
        for (int kp = 0; kp < 8; kp++) {
            uint32_t aq[4];
            uint32_t qa = sb + (kp >> 2) * TILEB + (w * 16 + ar) * 128
                        + ((((kp & 3) * 2 + asel) ^ sw) << 4);
            ldsm4(aq[0], aq[1], aq[2], aq[3], qa);
            #pragma unroll
            for (int nb = 0; nb < 8; nb++) {
                uint32_t b0, b1, b2, b3;
                uint32_t ka = sK + (kp >> 2) * TILEB + (nb * 16 + br) * 128
                            + ((((kp & 3) * 2 + bsel) ^ sw) << 4);
                ldsm4(b0, b1, b2, b3, ka);
                mma16816(sacc[nb * 2],     aq, b0, b1);
                mma16816(sacc[nb * 2 + 1], aq, b2, b3);
            }
        }

        #pragma unroll
        for (int i = 0; i < 16; i++)
            #pragma unroll
            for (int c = 0; c < 4; c++) sacc[i][c] *= alpha;
        if (by == j) {
            int r0 = w * 16 + (l >> 2);
            #pragma unroll
            for (int nt = 0; nt < 16; nt++) {
                int cb = nt * 8 + (l & 3) * 2;
                if (cb     == r0)     sacc[nt][0] = 0.0f;
                if (cb + 1 == r0)     sacc[nt][1] = 0.0f;
                if (cb     == r0 + 8) sacc[nt][2] = 0.0f;
                if (cb + 1 == r0 + 8) sacc[nt][3] = 0.0f;
            }
        }

        #pragma unroll
        for (int g = 0; g < 2; g++) {
            float mx = -1e30f;
            #pragma unroll
            for (int nt = 0; nt < 16; nt++)
                mx = fmaxf(mx, fmaxf(sacc[nt][2 * g], sacc[nt][2 * g + 1]));
            mx = fmaxf(mx, __shfl_xor_sync(0xffffffffu, mx, 1));
            mx = fmaxf(mx, __shfl_xor_sync(0xffffffffu, mx, 2));
            float mnew = fmaxf(mprev[g], mx);
            float sc = __expf(mprev[g] - mnew);
            float sum = 0.0f;
            #pragma unroll
            for (int nt = 0; nt < 16; nt++) {
                float e0 = __expf(sacc[nt][2 * g]     - mnew);
                float e1 = __expf(sacc[nt][2 * g + 1] - mnew);
                sacc[nt][2 * g] = e0; sacc[nt][2 * g + 1] = e1;
                sum += e0 + e1;
            }
            sum += __shfl_xor_sync(0xffffffffu, sum, 1);
            sum += __shfl_xor_sync(0xffffffffu, sum, 2);
            lsum[g] = lsum[g] * sc + sum;
            mprev[g] = mnew;
            #pragma unroll
            for (int nt = 0; nt < 16; nt++) {
                oacc[nt][2 * g]     *= sc;
                oacc[nt][2 * g + 1] *= sc;
            }
        }

        uint32_t aP[8][4];
        #pragma unroll
        for (int t = 0; t < 8; t++) {
            aP[t][0] = f2h2(sacc[2*t][0],   sacc[2*t][1]);
            aP[t][1] = f2h2(sacc[2*t][2],   sacc[2*t][3]);
            aP[t][2] = f2h2(sacc[2*t+1][0], sacc[2*t+1][1]);
            aP[t][3] = f2h2(sacc[2*t+1][2], sacc[2*t+1][3]);
        }

        #pragma unroll
        for (int t = 0; t < 8; t++) {
            #pragma unroll
            for (int nb = 0; nb < 8; nb++) {
                uint32_t b0, b1, b2, b3;
                uint32_t va = sV + (t >> 2) * TILEB + (nb * 16 + br) * 128
                            + ((((t & 3) * 2 + bsel) ^ sw) << 4);
                ldsm4(b0, b1, b2, b3, va);
                mma16816(oacc[nb * 2],     aP[t], b0, b1);
                mma16816(oacc[nb * 2 + 1], aP[t], b2, b3);
            }
        }
        __syncthreads();
    }

    #pragma unroll
    for (int g = 0; g < 2; g++) {
        float inv = 1.0f / lsum[g];
        long m = qrow0 + w * 16 + (l >> 2) + 8 * g;
        f16* op = outp + m * Hc + h * HDc + (l & 3) * 2;
        #pragma unroll
        for (int nt = 0; nt < 16; nt++) {
            float v0 = oacc[nt][2 * g] * inv, v1 = oacc[nt][2 * g + 1] * inv;
            *(__half2*)(op + nt * 8) = __halves2half2(__float2half(v0), __float2half(v1));
        }
    }
}

// ---------------------------------------------------------------------------
// Launch
// ---------------------------------------------------------------------------
extern "C" void kernel_launch(void* const* d_in, const int* in_sizes, int n_in,
                              void* d_out, int out_size)
{
    const float* x      = (const float*)d_in[0];
    const float* conv_w = (const float*)d_in[1];
    const float* conv_b = (const float*)d_in[2];
    const float* w1 = (const float*)d_in[3];
    const float* b1 = (const float*)d_in[4];
    const float* w2 = (const float*)d_in[5];
    const float* b2 = (const float*)d_in[6];
    const float* ln_g = (const float*)d_in[7];
    const float* ln_b = (const float*)d_in[8];
    const float* wq = (const float*)d_in[9];
    const float* bq = (const float*)d_in[10];
    const float* wk = (const float*)d_in[11];
    const float* bk = (const float*)d_in[12];
    const float* wv = (const float*)d_in[13];
    const float* bv = (const float*)d_in[14];
    const float* wo = (const float*)d_in[15];
    const float* bo = (const float*)d_in[16];
    const float* wp = (const float*)d_in[17];
    const float* bp = (const float*)d_in[18];
    float* out = (float*)d_out;

    #define SYM(p, s) void* p; cudaGetSymbolAddress(&p, s)
    SYM(xah, g_xah);
    SYM(h1, g_h1);
    SYM(xreg, g_xreg);
    SYM(xnh, g_xnh);
    SYM(qkv, g_qkv); SYM(vth, g_vth);
    SYM(ch, g_ch);
    SYM(w1t, g_w1t); SYM(w2t, g_w2t);
    SYM(wqkv, g_wqkv); SYM(bqkv, g_bqkv);
    SYM(wo16, g_wo16); SYM(wpt, g_wpt); SYM(wopT, g_wopT); SYM(bop, g_bop);
    #undef SYM

    const int SMB_1 = NST * 2 * TILEB;   //  98304
    const int SMB_F = 10 * TILEB;        // 163840
    cudaFuncSetAttribute(mmk<1,3>, cudaFuncAttributeMaxDynamicSharedMemorySize, SMB_1);
    cudaFuncSetAttribute(mmk<0,1>, cudaFuncAttributeMaxDynamicSharedMemorySize, SMB_1);
    cudaFuncSetAttribute(mmk<1,1>, cudaFuncAttributeMaxDynamicSharedMemorySize, SMB_1);
    cudaFuncSetAttribute(mmk<1,0>, cudaFuncAttributeMaxDynamicSharedMemorySize, SMB_1);
    cudaFuncSetAttribute(mmk<0,5>, cudaFuncAttributeMaxDynamicSharedMemorySize, SMB_1);
    cudaFuncSetAttribute(fattn, cudaFuncAttributeMaxDynamicSharedMemorySize, SMB_F);

    const int BMrows = Bc * Mc;  // 32768

    // 1. conv means, affine -> fp16
    means_k<<<1, 1024>>>(conv_w, conv_b);
    affine_k<<<(unsigned)(BMM / 4 / 256), 256>>>((const float4*)x, (f16*)xah);

    // 2. weight prep: transposes for GEMM B operands, plain cast for wo,
    //    fused biases
    wsplit1<<<dim3(Mc/32, Hc/32), dim3(32,8)>>>(w1, (f16*)w1t, Mc, Hc);
    wsplit1<<<dim3(Hc/32, Hc/32), dim3(32,8)>>>(w2, (f16*)w2t, Hc, Hc);
    wsplit1<<<dim3(Hc/32, Hc/32), dim3(32,8)>>>(wq, (f16*)wqkv,                   Hc, Hc);
    wsplit1<<<dim3(Hc/32, Hc/32), dim3(32,8)>>>(wk, (f16*)wqkv + (size_t)Hc*Hc,   Hc, Hc);
    wsplit1<<<dim3(Hc/32, Hc/32), dim3(32,8)>>>(wv, (f16*)wqkv + (size_t)2*Hc*Hc, Hc, Hc);
    wcast<<<Hc*Hc/4/256, 256>>>((const float4*)wo, (f16*)wo16);
    wsplit1<<<dim3(Hc/32, Hc/32), dim3(32,8)>>>(wp, (f16*)wpt, Hc, Hc);
    bcat<<<12, 256>>>(bq, bk, bv, (float*)bqkv);
    bop_k<<<4, 256>>>(bo, wp, bp, (float*)bop);

    // 3. wopT[n,j] = sum_k wpt[n,k] * wo16[j,k] = sum_k wp[k,n] wo[j,k]
    //    = (wo@wp)[j,n]  -> exactly the [N,K] B-layout for the final GEMM
    mmk<1,0><<<dim3(Hc/128, Hc/128, 1), 256, SMB_1>>>(
        (f16*)wpt, (f16*)wo16, nullptr, nullptr, nullptr, (f16*)wopT,
        Hc, Hc, Hc, Hc, 1, 0,0,0,0,0,0, 1.0f);

    // 4. h1 = relu(xa @ w1 + b1) -> fp16
    mmk<1,3><<<dim3(Hc/128, BMrows/128, 1), 256, SMB_1>>>(
        (f16*)xah, (f16*)w1t, b1, nullptr, nullptr, (f16*)h1,
        Mc, Mc, Mc, Hc, 1, 0,0,0,0,0,0, 1.0f);

    // 5. xreg = h1 @ w2 + b2 (fp32)
    mmk<0,1><<<dim3(Hc/128, BMrows/128, 1), 256, SMB_1>>>(
        (f16*)h1, (f16*)w2t, b2, nullptr, (float*)xreg, nullptr,
        Hc, Hc, Hc, Hc, 1, 0,0,0,0,0,0, 1.0f);

    // 6. layernorm -> fp16
    ln_k<<<BMrows, 256>>>((const float*)xreg, ln_g, ln_b, (f16*)xnh);

    // 7. fused q|k|v projection
    mmk<1,1><<<dim3(3*Hc/128, BMrows/128, 1), 256, SMB_1>>>(
        (f16*)xnh, (f16*)wqkv, (const float*)bqkv, nullptr, nullptr, (f16*)qkv,
        Hc, Hc, Hc, 3*Hc, 1, 0,0,0,0,0,0, 1.0f);

    // 8. vT fp16 [B*NH, HD, M]
    vsplitT<<<dim3(Mc/32, HDc/32, Bc*NHc), dim3(32,8)>>>((const f16*)qkv, (f16*)vth);

    // 9. fused attention -> ch
    fattn<<<dim3(Mc/128, Bc*NHc), 256, SMB_F>>>((const f16*)qkv, (const f16*)vth, (f16*)ch);

    // 10. out = ctx @ (wo@wp) + (bo@wp + bp) + xreg (fp32)
    mmk<0,5><<<dim3(Hc/128, BMrows/128, 1), 256, SMB_1>>>(
        (f16*)ch, (f16*)wopT, (const float*)bop, (const float*)xreg, out, nullptr,
        Hc, Hc, Hc, Hc, 1, 0,0,0,0,0,0, 1.0f);
}